// round 11
// baseline (speedup 1.0000x reference)
#include <cuda_runtime.h>
#include <cuda_bf16.h>
#include <cuda_fp16.h>
#include <cstdint>

#define NNODES 100000
#define D 128
#define EMAX 2000000
#define BN_EPS 1e-5f

// ---------------- device scratch (no dynamic allocation allowed) ----------------
__device__ __half g_hh[(size_t)NNODES * D];   // h' = dinv * (x @ W^T), fp16 (25.6 MB)
__device__ float g_dinv[NNODES];              // 1/sqrt(deg)
__device__ int   g_counts[NNODES];            // in-degree (excluding self loop)
__device__ int   g_rowstart[NNODES];          // CSR row offsets
__device__ int   g_cursor[NNODES];            // fill cursors
__device__ int   g_csr[EMAX];                 // CSR column (src) indices
__device__ int   g_blocksums[128];            // scan partials (per scan1 block)
__device__ float g_stats[2 * D];              // sums / sumsq
__device__ int   g_is64;                      // edge_index dtype flag
// W split into bf16 hi/lo, stored pre-swizzled (ldmatrix layout), 32KB each
__device__ __align__(16) __nv_bfloat16 g_Whi_img[16384];
__device__ __align__(16) __nv_bfloat16 g_Wlo_img[16384];

// ---------------- warp-mma helpers (plain sm_80+ PTX, no 'a'-gated features) -----
__device__ __forceinline__ uint32_t smem_u32(const void* p) {
    uint32_t a;
    asm("{ .reg .u64 t; cvta.to.shared.u64 t, %1; cvt.u32.u64 %0, t; }" : "=r"(a) : "l"(p));
    return a;
}
__device__ __forceinline__ void ldm_x4(uint32_t& r0, uint32_t& r1, uint32_t& r2, uint32_t& r3,
                                       uint32_t addr) {
    asm volatile("ldmatrix.sync.aligned.m8n8.x4.shared.b16 {%0,%1,%2,%3}, [%4];"
                 : "=r"(r0), "=r"(r1), "=r"(r2), "=r"(r3) : "r"(addr));
}
__device__ __forceinline__ void mma_bf16(float* c, const uint32_t* a, const uint32_t* b) {
    asm volatile(
        "mma.sync.aligned.m16n8k16.row.col.f32.bf16.bf16.f32 "
        "{%0,%1,%2,%3},{%4,%5,%6,%7},{%8,%9},{%0,%1,%2,%3};"
        : "+f"(c[0]), "+f"(c[1]), "+f"(c[2]), "+f"(c[3])
        : "r"(a[0]), "r"(a[1]), "r"(a[2]), "r"(a[3]), "r"(b[0]), "r"(b[1]));
}

// ---------------- edge index access (dtype detected at runtime) ----------------
__device__ __forceinline__ int edge_at(const void* ei, long long pos) {
    if (g_is64) return (int)((const long long*)ei)[pos];
    return ((const int*)ei)[pos];
}

// init: counters zero + dtype detect + stats zero + fused W hi/lo split
__global__ void k_init(const int* ei32, const float* __restrict__ W, int E, int N) {
    int i = blockIdx.x * blockDim.x + threadIdx.x;
    if (blockIdx.x == 0 && threadIdx.x < 32) {
        // int64 little-endian => odd int32 words of first 64 pairs are all zero
        int lane = threadIdx.x;
        int bad = 0;
        if (lane < E && ei32[2 * lane + 1] != 0) bad = 1;
        int k2 = lane + 32;
        if (k2 < E && k2 < 64 && ei32[2 * k2 + 1] != 0) bad = 1;
        unsigned m = __ballot_sync(0xffffffffu, bad);
        if (lane == 0) g_is64 = (m == 0u);
    }
    if (i < N) g_counts[i] = 0;
    if (i < 2 * D) g_stats[i] = 0.0f;
    if (i < 16384) {
        int r = i >> 7, k = i & 127;
        float w = W[i];
        __nv_bfloat16 hi = __float2bfloat16(w);
        __nv_bfloat16 lo = __float2bfloat16(w - __bfloat162float(hi));
        int kc = k >> 3;
        int idx = (r * 16 + (kc ^ (r & 7))) * 8 + (k & 7);
        g_Whi_img[idx] = hi;
        g_Wlo_img[idx] = lo;
    }
}

// hist: 2 edges/thread, vectorized loads
__global__ void k_hist(const void* ei, int E) {
    int e2 = (blockIdx.x * blockDim.x + threadIdx.x) * 2;
    if (e2 >= E) return;
    if (g_is64) {
        const long long* p = (const long long*)ei + E + e2;
        if (e2 + 1 < E) {
            longlong2 v = *(const longlong2*)p;     // 16B aligned: E, e2 even
            atomicAdd(&g_counts[(int)v.x], 1);
            atomicAdd(&g_counts[(int)v.y], 1);
        } else {
            atomicAdd(&g_counts[(int)p[0]], 1);
        }
    } else {
        const int* p = (const int*)ei + E + e2;
        if (e2 + 1 < E) {
            int2 v = *(const int2*)p;
            atomicAdd(&g_counts[v.x], 1);
            atomicAdd(&g_counts[v.y], 1);
        } else {
            atomicAdd(&g_counts[p[0]], 1);
        }
    }
}

// ---- proven two-kernel scan over g_counts -> g_rowstart ----
__global__ void k_scan1(int N) {
    __shared__ int warp_off[32];
    int t = threadIdx.x;
    int gid = blockIdx.x * 1024 + t;
    int v = (gid < N) ? g_counts[gid] : 0;
    int lane = t & 31, wid = t >> 5;
    int s = v;
#pragma unroll
    for (int off = 1; off < 32; off <<= 1) {
        int n2 = __shfl_up_sync(0xffffffffu, s, off);
        if (lane >= off) s += n2;
    }
    if (lane == 31) warp_off[wid] = s;
    __syncthreads();
    if (wid == 0) {
        int ws = warp_off[lane];
        int ss = ws;
#pragma unroll
        for (int off = 1; off < 32; off <<= 1) {
            int n2 = __shfl_up_sync(0xffffffffu, ss, off);
            if (lane >= off) ss += n2;
        }
        warp_off[lane] = ss - ws;
        if (lane == 31) g_blocksums[blockIdx.x] = ss;
    }
    __syncthreads();
    if (gid < N) g_rowstart[gid] = s + warp_off[wid] - v;
}

// scan3: grid 1:1 with scan1 blocks; warp 0 computes the blocksum prefix once.
__global__ __launch_bounds__(1024) void k_scan3(int N) {
    __shared__ int s_off;
    int t = threadIdx.x;
    int b = blockIdx.x;
    if (t < 32) {
        int acc = 0;
#pragma unroll
        for (int j = 0; j < 4; j++) {
            int idx = t + j * 32;
            if (idx < b) acc += g_blocksums[idx];
        }
#pragma unroll
        for (int off = 16; off > 0; off >>= 1)
            acc += __shfl_down_sync(0xffffffffu, acc, off);
        if (t == 0) s_off = acc;
    }
    __syncthreads();
    int i = blockIdx.x * 1024 + t;
    if (i >= N) return;
    int rs = g_rowstart[i] + s_off;
    g_rowstart[i] = rs;
    g_cursor[i]   = rs;
    g_dinv[i]     = rsqrtf((float)g_counts[i] + 1.0f);
}

// fill: 2 edges/thread, vectorized loads, bounds-guarded stores
__global__ void k_fill(const void* ei, int E) {
    int e2 = (blockIdx.x * blockDim.x + threadIdx.x) * 2;
    if (e2 >= E) return;
    int s0, d0, s1 = 0, d1 = 0;
    bool has2 = (e2 + 1 < E);
    if (g_is64) {
        const long long* p = (const long long*)ei;
        if (has2) {
            longlong2 vs = *(const longlong2*)(p + e2);
            longlong2 vd = *(const longlong2*)(p + E + e2);
            s0 = (int)vs.x; s1 = (int)vs.y; d0 = (int)vd.x; d1 = (int)vd.y;
        } else {
            s0 = (int)p[e2]; d0 = (int)p[E + e2];
        }
    } else {
        const int* p = (const int*)ei;
        if (has2) {
            int2 vs = *(const int2*)(p + e2);
            int2 vd = *(const int2*)(p + E + e2);
            s0 = vs.x; s1 = vs.y; d0 = vd.x; d1 = vd.y;
        } else {
            s0 = p[e2]; d0 = p[E + e2];
        }
    }
    int p0 = atomicAdd(&g_cursor[d0], 1);
    if (p0 < EMAX) g_csr[p0] = s0;
    if (has2) {
        int p1 = atomicAdd(&g_cursor[d1], 1);
        if (p1 < EMAX) g_csr[p1] = s1;
    }
}

// ------ GEMM: h' = dinv * (x @ W^T) -> fp16, 64-row tiles, 2 CTAs/SM -------------
#define SM_AHI 0
#define SM_ALO 16384
#define SM_BHI 32768
#define SM_BLO 65536
#define SM_TOT 98304

__global__ __launch_bounds__(256) void k_gemm_mma(const float* __restrict__ x, int N) {
    extern __shared__ char smem[];
    uint32_t sb = smem_u32(smem);
    int tid = threadIdx.x;
    int row0 = blockIdx.x * 64;

    {
        const uint4* wh = (const uint4*)g_Whi_img;
        const uint4* wl = (const uint4*)g_Wlo_img;
        uint4* bh = (uint4*)(smem + SM_BHI);
        uint4* bl = (uint4*)(smem + SM_BLO);
        for (int i = tid; i < 2048; i += 256) { bh[i] = wh[i]; bl[i] = wl[i]; }
    }

    {
        int r = tid >> 2;
        int q = tid & 3;
        int gr = row0 + r;
        char* Ah = smem + SM_AHI;
        char* Al = smem + SM_ALO;
        if (gr < N) {
            const float4* xr = (const float4*)(x + (size_t)gr * 128) + q * 8;
#pragma unroll
            for (int j = 0; j < 4; j++) {
                float4 v0 = xr[2 * j];
                float4 v1 = xr[2 * j + 1];
                float f[8] = {v0.x, v0.y, v0.z, v0.w, v1.x, v1.y, v1.z, v1.w};
                uint32_t hw[4], lw[4];
#pragma unroll
                for (int p = 0; p < 4; p++) {
                    float a = f[2 * p], b = f[2 * p + 1];
                    __nv_bfloat16 ha = __float2bfloat16(a);
                    __nv_bfloat16 hb = __float2bfloat16(b);
                    union { __nv_bfloat162 v; uint32_t u; } ch, cl;
                    ch.v = __nv_bfloat162(ha, hb);
                    cl.v = __nv_bfloat162(__float2bfloat16(a - __bfloat162float(ha)),
                                          __float2bfloat16(b - __bfloat162float(hb)));
                    hw[p] = ch.u;
                    lw[p] = cl.u;
                }
                int kc = q * 4 + j;
                int off = (r * 16 + (kc ^ (r & 7))) * 16;
                *(uint4*)(Ah + off) = make_uint4(hw[0], hw[1], hw[2], hw[3]);
                *(uint4*)(Al + off) = make_uint4(lw[0], lw[1], lw[2], lw[3]);
            }
        } else {
            uint4 z = make_uint4(0, 0, 0, 0);
#pragma unroll
            for (int j = 0; j < 4; j++) {
                int kc = q * 4 + j;
                int off = (r * 16 + (kc ^ (r & 7))) * 16;
                *(uint4*)(smem + SM_AHI + off) = z;
                *(uint4*)(smem + SM_ALO + off) = z;
            }
        }
    }
    __syncthreads();

    int warp = tid >> 5, lane = tid & 31;
    int wm = warp & 1, wn = warp >> 1;
    int m0 = wm * 32, n0 = wn * 32;
    int sub = lane >> 3, lrow = lane & 7;

    float acc[2][4][4];
#pragma unroll
    for (int mt = 0; mt < 2; mt++)
#pragma unroll
        for (int nt = 0; nt < 4; nt++)
#pragma unroll
            for (int q = 0; q < 4; q++) acc[mt][nt][q] = 0.f;

    int a_row_off = ((sub & 1) << 3) + lrow;
    int a_halfk   = sub >> 1;
    int b_row_off = ((sub & 2) << 2) + lrow;
    int b_halfk   = sub & 1;

#pragma unroll
    for (int ks = 0; ks < 8; ks++) {
        uint32_t ah[2][4], al[2][4], bh[4][2], bl[4][2];
#pragma unroll
        for (int mt = 0; mt < 2; mt++) {
            int r = m0 + mt * 16 + a_row_off;
            int kc = 2 * ks + a_halfk;
            uint32_t addr = (uint32_t)((r * 16 + (kc ^ (r & 7))) * 16);
            ldm_x4(ah[mt][0], ah[mt][1], ah[mt][2], ah[mt][3], sb + SM_AHI + addr);
            ldm_x4(al[mt][0], al[mt][1], al[mt][2], al[mt][3], sb + SM_ALO + addr);
        }
#pragma unroll
        for (int np = 0; np < 2; np++) {
            int r = n0 + np * 16 + b_row_off;
            int kc = 2 * ks + b_halfk;
            uint32_t addr = (uint32_t)((r * 16 + (kc ^ (r & 7))) * 16);
            ldm_x4(bh[2 * np][0], bh[2 * np][1], bh[2 * np + 1][0], bh[2 * np + 1][1],
                   sb + SM_BHI + addr);
            ldm_x4(bl[2 * np][0], bl[2 * np][1], bl[2 * np + 1][0], bl[2 * np + 1][1],
                   sb + SM_BLO + addr);
        }
#pragma unroll
        for (int mt = 0; mt < 2; mt++)
#pragma unroll
            for (int nt = 0; nt < 4; nt++) {
                mma_bf16(acc[mt][nt], ah[mt], bh[nt]);
                mma_bf16(acc[mt][nt], ah[mt], bl[nt]);
                mma_bf16(acc[mt][nt], al[mt], bh[nt]);
            }
    }

    int qrow = lane >> 2, qcol = (lane & 3) * 2;
    __half2* h2 = (__half2*)g_hh;
#pragma unroll
    for (int mt = 0; mt < 2; mt++) {
        int r_lo = row0 + m0 + mt * 16 + qrow;
        int r_hi = r_lo + 8;
        float d_lo = (r_lo < N) ? g_dinv[r_lo] : 0.f;
        float d_hi = (r_hi < N) ? g_dinv[r_hi] : 0.f;
#pragma unroll
        for (int nt = 0; nt < 4; nt++) {
            int col = n0 + nt * 8 + qcol;
            if (r_lo < N)
                h2[(size_t)r_lo * 64 + (col >> 1)] =
                    __floats2half2_rn(d_lo * acc[mt][nt][0], d_lo * acc[mt][nt][1]);
            if (r_hi < N)
                h2[(size_t)r_hi * 64 + (col >> 1)] =
                    __floats2half2_rn(d_hi * acc[mt][nt][2], d_hi * acc[mt][nt][3]);
        }
    }
}

// ------- aggregation (grid-stride, warp per node) + fused BN statistics ----------
__global__ __launch_bounds__(256) void k_agg(const float* __restrict__ bias,
                                             float* __restrict__ out, int N, int totalWarps) {
    __shared__ float sh_sum[128];
    __shared__ float sh_sq[128];
    int tid = threadIdx.x;
    int lane = tid & 31;
    if (tid < 128) { sh_sum[tid] = 0.f; sh_sq[tid] = 0.f; }
    __syncthreads();

    int gwarp = blockIdx.x * 8 + (tid >> 5);
    const uint2* hrow = (const uint2*)g_hh;   // 32 uint2 per 128-half row
    float4 bb = ((const float4*)bias)[lane];
    float4 ssum = make_float4(0.f, 0.f, 0.f, 0.f);
    float4 ssq  = make_float4(0.f, 0.f, 0.f, 0.f);

    for (int node = gwarp; node < N; node += totalWarps) {
        int   base = g_rowstart[node];
        int   cnt  = g_counts[node];
        float di   = g_dinv[node];

        float4 a0, a1, a2, a3;
        {
            uint2 v = hrow[(size_t)node * 32 + lane];
            float2 p0 = __half22float2(*(__half2*)&v.x);
            float2 p1 = __half22float2(*(__half2*)&v.y);
            a0 = make_float4(p0.x, p0.y, p1.x, p1.y);
        }
        a1 = make_float4(0.f, 0.f, 0.f, 0.f);
        a2 = make_float4(0.f, 0.f, 0.f, 0.f);
        a3 = make_float4(0.f, 0.f, 0.f, 0.f);

        for (int j0 = 0; j0 < cnt; j0 += 32) {
            int myj = j0 + lane;
            int s = (myj < cnt) ? g_csr[base + myj] : 0;
            int m = min(32, cnt - j0);
            int t = 0;
            // 8 independent gathers in flight
            for (; t + 8 <= m; t += 8) {
                int sv0 = __shfl_sync(0xffffffffu, s, t);
                int sv1 = __shfl_sync(0xffffffffu, s, t + 1);
                int sv2 = __shfl_sync(0xffffffffu, s, t + 2);
                int sv3 = __shfl_sync(0xffffffffu, s, t + 3);
                int sv4 = __shfl_sync(0xffffffffu, s, t + 4);
                int sv5 = __shfl_sync(0xffffffffu, s, t + 5);
                int sv6 = __shfl_sync(0xffffffffu, s, t + 6);
                int sv7 = __shfl_sync(0xffffffffu, s, t + 7);
                uint2 v0 = hrow[(size_t)sv0 * 32 + lane];
                uint2 v1 = hrow[(size_t)sv1 * 32 + lane];
                uint2 v2 = hrow[(size_t)sv2 * 32 + lane];
                uint2 v3 = hrow[(size_t)sv3 * 32 + lane];
                uint2 v4 = hrow[(size_t)sv4 * 32 + lane];
                uint2 v5 = hrow[(size_t)sv5 * 32 + lane];
                uint2 v6 = hrow[(size_t)sv6 * 32 + lane];
                uint2 v7 = hrow[(size_t)sv7 * 32 + lane];
                float2 q0, q1;
                q0 = __half22float2(*(__half2*)&v0.x); q1 = __half22float2(*(__half2*)&v0.y);
                a0.x += q0.x; a0.y += q0.y; a0.z += q1.x; a0.w += q1.y;
                q0 = __half22float2(*(__half2*)&v1.x); q1 = __half22float2(*(__half2*)&v1.y);
                a1.x += q0.x; a1.y += q0.y; a1.z += q1.x; a1.w += q1.y;
                q0 = __half22float2(*(__half2*)&v2.x); q1 = __half22float2(*(__half2*)&v2.y);
                a2.x += q0.x; a2.y += q0.y; a2.z += q1.x; a2.w += q1.y;
                q0 = __half22float2(*(__half2*)&v3.x); q1 = __half22float2(*(__half2*)&v3.y);
                a3.x += q0.x; a3.y += q0.y; a3.z += q1.x; a3.w += q1.y;
                q0 = __half22float2(*(__half2*)&v4.x); q1 = __half22float2(*(__half2*)&v4.y);
                a0.x += q0.x; a0.y += q0.y; a0.z += q1.x; a0.w += q1.y;
                q0 = __half22float2(*(__half2*)&v5.x); q1 = __half22float2(*(__half2*)&v5.y);
                a1.x += q0.x; a1.y += q0.y; a1.z += q1.x; a1.w += q1.y;
                q0 = __half22float2(*(__half2*)&v6.x); q1 = __half22float2(*(__half2*)&v6.y);
                a2.x += q0.x; a2.y += q0.y; a2.z += q1.x; a2.w += q1.y;
                q0 = __half22float2(*(__half2*)&v7.x); q1 = __half22float2(*(__half2*)&v7.y);
                a3.x += q0.x; a3.y += q0.y; a3.z += q1.x; a3.w += q1.y;
            }
            for (; t < m; t++) {
                int sv0 = __shfl_sync(0xffffffffu, s, t);
                uint2 v0 = hrow[(size_t)sv0 * 32 + lane];
                float2 q0 = __half22float2(*(__half2*)&v0.x);
                float2 q1 = __half22float2(*(__half2*)&v0.y);
                a0.x += q0.x; a0.y += q0.y; a0.z += q1.x; a0.w += q1.y;
            }
        }
        float4 o;
        o.x = di * ((a0.x + a1.x) + (a2.x + a3.x)) + bb.x;
        o.y = di * ((a0.y + a1.y) + (a2.y + a3.y)) + bb.y;
        o.z = di * ((a0.z + a1.z) + (a2.z + a3.z)) + bb.z;
        o.w = di * ((a0.w + a1.w) + (a2.w + a3.w)) + bb.w;
        ((float4*)out)[(size_t)node * 32 + lane] = o;
        ssum.x += o.x; ssum.y += o.y; ssum.z += o.z; ssum.w += o.w;
        ssq.x += o.x * o.x; ssq.y += o.y * o.y; ssq.z += o.z * o.z; ssq.w += o.w * o.w;
    }

    atomicAdd(&sh_sum[lane * 4 + 0], ssum.x);
    atomicAdd(&sh_sum[lane * 4 + 1], ssum.y);
    atomicAdd(&sh_sum[lane * 4 + 2], ssum.z);
    atomicAdd(&sh_sum[lane * 4 + 3], ssum.w);
    atomicAdd(&sh_sq[lane * 4 + 0], ssq.x);
    atomicAdd(&sh_sq[lane * 4 + 1], ssq.y);
    atomicAdd(&sh_sq[lane * 4 + 2], ssq.z);
    atomicAdd(&sh_sq[lane * 4 + 3], ssq.w);
    __syncthreads();
    if (tid < 128) {
        atomicAdd(&g_stats[tid], sh_sum[tid]);
        atomicAdd(&g_stats[D + tid], sh_sq[tid]);
    }
}

// ---------------- BN + ReLU + residual -------------------------------------------
__global__ void k_final(const float* __restrict__ x, const float* __restrict__ gamma,
                        const float* __restrict__ beta, float* __restrict__ out, int N) {
    long long i = (long long)blockIdx.x * blockDim.x + threadIdx.x;
    long long total = (long long)N * 32;
    if (i >= total) return;
    int c4 = (int)(i & 31);
    float invN = 1.0f / (float)N;
    float4 v  = ((float4*)out)[i];
    float4 xv = ((const float4*)x)[i];
    float r[4] = {v.x, v.y, v.z, v.w};
    float xr[4] = {xv.x, xv.y, xv.z, xv.w};
#pragma unroll
    for (int c = 0; c < 4; c++) {
        int col = c4 * 4 + c;
        float mu  = g_stats[col] * invN;
        float var = g_stats[D + col] * invN - mu * mu;
        float inv = rsqrtf(var + BN_EPS);
        float y = __ldg(&gamma[col]) * (r[c] - mu) * inv + __ldg(&beta[col]);
        y = fmaxf(y, 0.0f);
        r[c] = y + xr[c];
    }
    ((float4*)out)[i] = make_float4(r[0], r[1], r[2], r[3]);
}

// ---------------- launcher --------------------------------------------------------
extern "C" void kernel_launch(void* const* d_in, const int* in_sizes, int n_in,
                              void* d_out, int out_size) {
    const float* x     = (const float*)d_in[0];
    const float* W     = (const float*)d_in[1];
    const float* bias  = (const float*)d_in[2];
    const float* gamma = (const float*)d_in[3];
    const float* beta  = (const float*)d_in[4];
    const void*  ei    = d_in[5];
    int N = in_sizes[0] / D;
    int E = in_sizes[5] / 2;
    float* out = (float*)d_out;

    cudaFuncSetAttribute(k_gemm_mma, cudaFuncAttributeMaxDynamicSharedMemorySize, SM_TOT);

    int epairs = (E + 1) / 2;
    int nblk = (N + 1023) / 1024;
    k_init<<<(N + 255) / 256, 256>>>((const int*)ei, W, E, N);
    k_hist<<<(epairs + 255) / 256, 256>>>(ei, E);
    k_scan1<<<nblk, 1024>>>(N);
    k_scan3<<<nblk, 1024>>>(N);
    k_fill<<<(epairs + 255) / 256, 256>>>(ei, E);
    k_gemm_mma<<<(N + 63) / 64, 256, SM_TOT>>>(x, N);
    int aggBlocks = 1036;                       // 7 blocks/SM * 148
    k_agg<<<aggBlocks, 256>>>(bias, out, N, aggBlocks * 8);
    k_final<<<(int)(((long long)N * 32 + 255) / 256), 256>>>(x, gamma, beta, out, N);
}

// round 12
// speedup vs baseline: 1.1028x; 1.1028x over previous
#include <cuda_runtime.h>
#include <cuda_bf16.h>
#include <cuda_fp16.h>
#include <cstdint>

#define NNODES 100000
#define D 128
#define EMAX 2000000
#define BN_EPS 1e-5f

// ---------------- device scratch (no dynamic allocation allowed) ----------------
__device__ __half g_hh[(size_t)NNODES * D];   // h' = dinv * (x @ W^T), fp16 (25.6 MB)
__device__ float g_dinv[NNODES];              // 1/sqrt(deg)
__device__ int   g_counts[NNODES];            // in-degree (excluding self loop)
__device__ int   g_rowstart[NNODES];          // CSR row offsets
__device__ int   g_cursor[NNODES];            // fill cursors
__device__ int   g_csr[EMAX];                 // CSR column (src) indices
__device__ int   g_blocksums[128];            // scan partials (per scan1 block)
__device__ float g_stats[2 * D];              // sums / sumsq
__device__ int   g_is64;                      // edge_index dtype flag
// W split into bf16 hi/lo, stored pre-swizzled (ldmatrix layout), 32KB each
__device__ __align__(16) __nv_bfloat16 g_Whi_img[16384];
__device__ __align__(16) __nv_bfloat16 g_Wlo_img[16384];

// ---------------- warp-mma helpers (plain sm_80+ PTX, no 'a'-gated features) -----
__device__ __forceinline__ uint32_t smem_u32(const void* p) {
    uint32_t a;
    asm("{ .reg .u64 t; cvta.to.shared.u64 t, %1; cvt.u32.u64 %0, t; }" : "=r"(a) : "l"(p));
    return a;
}
__device__ __forceinline__ void ldm_x4(uint32_t& r0, uint32_t& r1, uint32_t& r2, uint32_t& r3,
                                       uint32_t addr) {
    asm volatile("ldmatrix.sync.aligned.m8n8.x4.shared.b16 {%0,%1,%2,%3}, [%4];"
                 : "=r"(r0), "=r"(r1), "=r"(r2), "=r"(r3) : "r"(addr));
}
__device__ __forceinline__ void mma_bf16(float* c, const uint32_t* a, const uint32_t* b) {
    asm volatile(
        "mma.sync.aligned.m16n8k16.row.col.f32.bf16.bf16.f32 "
        "{%0,%1,%2,%3},{%4,%5,%6,%7},{%8,%9},{%0,%1,%2,%3};"
        : "+f"(c[0]), "+f"(c[1]), "+f"(c[2]), "+f"(c[3])
        : "r"(a[0]), "r"(a[1]), "r"(a[2]), "r"(a[3]), "r"(b[0]), "r"(b[1]));
}

// ---------------- edge index access (dtype detected at runtime) ----------------
__device__ __forceinline__ int edge_at(const void* ei, long long pos) {
    if (g_is64) return (int)((const long long*)ei)[pos];
    return ((const int*)ei)[pos];
}

// init: counters zero + dtype detect + stats zero + fused W hi/lo split
__global__ void k_init(const int* ei32, const float* __restrict__ W, int E, int N) {
    int i = blockIdx.x * blockDim.x + threadIdx.x;
    if (blockIdx.x == 0 && threadIdx.x < 32) {
        // int64 little-endian => odd int32 words of first 64 pairs are all zero
        int lane = threadIdx.x;
        int bad = 0;
        if (lane < E && ei32[2 * lane + 1] != 0) bad = 1;
        int k2 = lane + 32;
        if (k2 < E && k2 < 64 && ei32[2 * k2 + 1] != 0) bad = 1;
        unsigned m = __ballot_sync(0xffffffffu, bad);
        if (lane == 0) g_is64 = (m == 0u);
    }
    if (i < N) g_counts[i] = 0;
    if (i < 2 * D) g_stats[i] = 0.0f;
    if (i < 16384) {
        int r = i >> 7, k = i & 127;
        float w = W[i];
        __nv_bfloat16 hi = __float2bfloat16(w);
        __nv_bfloat16 lo = __float2bfloat16(w - __bfloat162float(hi));
        int kc = k >> 3;
        int idx = (r * 16 + (kc ^ (r & 7))) * 8 + (k & 7);
        g_Whi_img[idx] = hi;
        g_Wlo_img[idx] = lo;
    }
}

// hist: 1 edge/thread (proven R8 form)
__global__ void k_hist(const void* ei, int E) {
    int e = blockIdx.x * blockDim.x + threadIdx.x;
    if (e >= E) return;
    int d = edge_at(ei, (long long)E + e);
    atomicAdd(&g_counts[d], 1);
}

// scan1: within-block exclusive scan; ALSO computes dinv (unblocks GEMM early)
__global__ void k_scan1(int N) {
    __shared__ int warp_off[32];
    int t = threadIdx.x;
    int gid = blockIdx.x * 1024 + t;
    int v = (gid < N) ? g_counts[gid] : 0;
    int lane = t & 31, wid = t >> 5;
    int s = v;
#pragma unroll
    for (int off = 1; off < 32; off <<= 1) {
        int n2 = __shfl_up_sync(0xffffffffu, s, off);
        if (lane >= off) s += n2;
    }
    if (lane == 31) warp_off[wid] = s;
    __syncthreads();
    if (wid == 0) {
        int ws = warp_off[lane];
        int ss = ws;
#pragma unroll
        for (int off = 1; off < 32; off <<= 1) {
            int n2 = __shfl_up_sync(0xffffffffu, ss, off);
            if (lane >= off) ss += n2;
        }
        warp_off[lane] = ss - ws;
        if (lane == 31) g_blocksums[blockIdx.x] = ss;
    }
    __syncthreads();
    if (gid < N) {
        g_rowstart[gid] = s + warp_off[wid] - v;
        g_dinv[gid]     = rsqrtf((float)v + 1.0f);
    }
}

// scan3: grid 1:1 with scan1 blocks; warp 0 computes the blocksum prefix once.
__global__ __launch_bounds__(1024) void k_scan3(int N) {
    __shared__ int s_off;
    int t = threadIdx.x;
    int b = blockIdx.x;
    if (t < 32) {
        int acc = 0;
#pragma unroll
        for (int j = 0; j < 4; j++) {
            int idx = t + j * 32;
            if (idx < b) acc += g_blocksums[idx];
        }
#pragma unroll
        for (int off = 16; off > 0; off >>= 1)
            acc += __shfl_down_sync(0xffffffffu, acc, off);
        if (t == 0) s_off = acc;
    }
    __syncthreads();
    int i = blockIdx.x * 1024 + t;
    if (i >= N) return;
    int rs = g_rowstart[i] + s_off;
    g_rowstart[i] = rs;
    g_cursor[i]   = rs;
}

// fill: 1 edge/thread (proven R8 form)
__global__ void k_fill(const void* ei, int E) {
    int e = blockIdx.x * blockDim.x + threadIdx.x;
    if (e >= E) return;
    int s = edge_at(ei, e);
    int d = edge_at(ei, (long long)E + e);
    int pos = atomicAdd(&g_cursor[d], 1);
    if (pos < EMAX) g_csr[pos] = s;
}

// ------ GEMM: h' = dinv * (x @ W^T) -> fp16, 64-row tiles, 2 CTAs/SM -------------
#define SM_AHI 0
#define SM_ALO 16384
#define SM_BHI 32768
#define SM_BLO 65536
#define SM_TOT 98304

__global__ __launch_bounds__(256) void k_gemm_mma(const float* __restrict__ x, int N) {
    extern __shared__ char smem[];
    uint32_t sb = smem_u32(smem);
    int tid = threadIdx.x;
    int row0 = blockIdx.x * 64;

    {
        const uint4* wh = (const uint4*)g_Whi_img;
        const uint4* wl = (const uint4*)g_Wlo_img;
        uint4* bh = (uint4*)(smem + SM_BHI);
        uint4* bl = (uint4*)(smem + SM_BLO);
        for (int i = tid; i < 2048; i += 256) { bh[i] = wh[i]; bl[i] = wl[i]; }
    }

    {
        int r = tid >> 2;
        int q = tid & 3;
        int gr = row0 + r;
        char* Ah = smem + SM_AHI;
        char* Al = smem + SM_ALO;
        if (gr < N) {
            const float4* xr = (const float4*)(x + (size_t)gr * 128) + q * 8;
#pragma unroll
            for (int j = 0; j < 4; j++) {
                float4 v0 = xr[2 * j];
                float4 v1 = xr[2 * j + 1];
                float f[8] = {v0.x, v0.y, v0.z, v0.w, v1.x, v1.y, v1.z, v1.w};
                uint32_t hw[4], lw[4];
#pragma unroll
                for (int p = 0; p < 4; p++) {
                    float a = f[2 * p], b = f[2 * p + 1];
                    __nv_bfloat16 ha = __float2bfloat16(a);
                    __nv_bfloat16 hb = __float2bfloat16(b);
                    union { __nv_bfloat162 v; uint32_t u; } ch, cl;
                    ch.v = __nv_bfloat162(ha, hb);
                    cl.v = __nv_bfloat162(__float2bfloat16(a - __bfloat162float(ha)),
                                          __float2bfloat16(b - __bfloat162float(hb)));
                    hw[p] = ch.u;
                    lw[p] = cl.u;
                }
                int kc = q * 4 + j;
                int off = (r * 16 + (kc ^ (r & 7))) * 16;
                *(uint4*)(Ah + off) = make_uint4(hw[0], hw[1], hw[2], hw[3]);
                *(uint4*)(Al + off) = make_uint4(lw[0], lw[1], lw[2], lw[3]);
            }
        } else {
            uint4 z = make_uint4(0, 0, 0, 0);
#pragma unroll
            for (int j = 0; j < 4; j++) {
                int kc = q * 4 + j;
                int off = (r * 16 + (kc ^ (r & 7))) * 16;
                *(uint4*)(smem + SM_AHI + off) = z;
                *(uint4*)(smem + SM_ALO + off) = z;
            }
        }
    }
    __syncthreads();

    int warp = tid >> 5, lane = tid & 31;
    int wm = warp & 1, wn = warp >> 1;
    int m0 = wm * 32, n0 = wn * 32;
    int sub = lane >> 3, lrow = lane & 7;

    float acc[2][4][4];
#pragma unroll
    for (int mt = 0; mt < 2; mt++)
#pragma unroll
        for (int nt = 0; nt < 4; nt++)
#pragma unroll
            for (int q = 0; q < 4; q++) acc[mt][nt][q] = 0.f;

    int a_row_off = ((sub & 1) << 3) + lrow;
    int a_halfk   = sub >> 1;
    int b_row_off = ((sub & 2) << 2) + lrow;
    int b_halfk   = sub & 1;

#pragma unroll
    for (int ks = 0; ks < 8; ks++) {
        uint32_t ah[2][4], al[2][4], bh[4][2], bl[4][2];
#pragma unroll
        for (int mt = 0; mt < 2; mt++) {
            int r = m0 + mt * 16 + a_row_off;
            int kc = 2 * ks + a_halfk;
            uint32_t addr = (uint32_t)((r * 16 + (kc ^ (r & 7))) * 16);
            ldm_x4(ah[mt][0], ah[mt][1], ah[mt][2], ah[mt][3], sb + SM_AHI + addr);
            ldm_x4(al[mt][0], al[mt][1], al[mt][2], al[mt][3], sb + SM_ALO + addr);
        }
#pragma unroll
        for (int np = 0; np < 2; np++) {
            int r = n0 + np * 16 + b_row_off;
            int kc = 2 * ks + b_halfk;
            uint32_t addr = (uint32_t)((r * 16 + (kc ^ (r & 7))) * 16);
            ldm_x4(bh[2 * np][0], bh[2 * np][1], bh[2 * np + 1][0], bh[2 * np + 1][1],
                   sb + SM_BHI + addr);
            ldm_x4(bl[2 * np][0], bl[2 * np][1], bl[2 * np + 1][0], bl[2 * np + 1][1],
                   sb + SM_BLO + addr);
        }
#pragma unroll
        for (int mt = 0; mt < 2; mt++)
#pragma unroll
            for (int nt = 0; nt < 4; nt++) {
                mma_bf16(acc[mt][nt], ah[mt], bh[nt]);
                mma_bf16(acc[mt][nt], ah[mt], bl[nt]);
                mma_bf16(acc[mt][nt], al[mt], bh[nt]);
            }
    }

    int qrow = lane >> 2, qcol = (lane & 3) * 2;
    __half2* h2 = (__half2*)g_hh;
#pragma unroll
    for (int mt = 0; mt < 2; mt++) {
        int r_lo = row0 + m0 + mt * 16 + qrow;
        int r_hi = r_lo + 8;
        float d_lo = (r_lo < N) ? g_dinv[r_lo] : 0.f;
        float d_hi = (r_hi < N) ? g_dinv[r_hi] : 0.f;
#pragma unroll
        for (int nt = 0; nt < 4; nt++) {
            int col = n0 + nt * 8 + qcol;
            if (r_lo < N)
                h2[(size_t)r_lo * 64 + (col >> 1)] =
                    __floats2half2_rn(d_lo * acc[mt][nt][0], d_lo * acc[mt][nt][1]);
            if (r_hi < N)
                h2[(size_t)r_hi * 64 + (col >> 1)] =
                    __floats2half2_rn(d_hi * acc[mt][nt][2], d_hi * acc[mt][nt][3]);
        }
    }
}

// ------- aggregation (grid-stride, warp per node) + fused BN statistics ----------
// proven R8 form: 4 independent gathers in flight
__global__ __launch_bounds__(256) void k_agg(const float* __restrict__ bias,
                                             float* __restrict__ out, int N, int totalWarps) {
    __shared__ float sh_sum[128];
    __shared__ float sh_sq[128];
    int tid = threadIdx.x;
    int lane = tid & 31;
    if (tid < 128) { sh_sum[tid] = 0.f; sh_sq[tid] = 0.f; }
    __syncthreads();

    int gwarp = blockIdx.x * 8 + (tid >> 5);
    const uint2* hrow = (const uint2*)g_hh;   // 32 uint2 per 128-half row
    float4 bb = ((const float4*)bias)[lane];
    float4 ssum = make_float4(0.f, 0.f, 0.f, 0.f);
    float4 ssq  = make_float4(0.f, 0.f, 0.f, 0.f);

    for (int node = gwarp; node < N; node += totalWarps) {
        int   base = g_rowstart[node];
        int   cnt  = g_counts[node];
        float di   = g_dinv[node];

        float4 a0, a1, a2, a3;
        {
            uint2 v = hrow[(size_t)node * 32 + lane];
            float2 p0 = __half22float2(*(__half2*)&v.x);
            float2 p1 = __half22float2(*(__half2*)&v.y);
            a0 = make_float4(p0.x, p0.y, p1.x, p1.y);
        }
        a1 = make_float4(0.f, 0.f, 0.f, 0.f);
        a2 = make_float4(0.f, 0.f, 0.f, 0.f);
        a3 = make_float4(0.f, 0.f, 0.f, 0.f);

        for (int j0 = 0; j0 < cnt; j0 += 32) {
            int myj = j0 + lane;
            int s = (myj < cnt) ? g_csr[base + myj] : 0;
            int m = min(32, cnt - j0);
            int t = 0;
            for (; t + 4 <= m; t += 4) {
                int sv0 = __shfl_sync(0xffffffffu, s, t);
                int sv1 = __shfl_sync(0xffffffffu, s, t + 1);
                int sv2 = __shfl_sync(0xffffffffu, s, t + 2);
                int sv3 = __shfl_sync(0xffffffffu, s, t + 3);
                uint2 v0 = hrow[(size_t)sv0 * 32 + lane];
                uint2 v1 = hrow[(size_t)sv1 * 32 + lane];
                uint2 v2 = hrow[(size_t)sv2 * 32 + lane];
                uint2 v3 = hrow[(size_t)sv3 * 32 + lane];
                float2 q0, q1;
                q0 = __half22float2(*(__half2*)&v0.x); q1 = __half22float2(*(__half2*)&v0.y);
                a0.x += q0.x; a0.y += q0.y; a0.z += q1.x; a0.w += q1.y;
                q0 = __half22float2(*(__half2*)&v1.x); q1 = __half22float2(*(__half2*)&v1.y);
                a1.x += q0.x; a1.y += q0.y; a1.z += q1.x; a1.w += q1.y;
                q0 = __half22float2(*(__half2*)&v2.x); q1 = __half22float2(*(__half2*)&v2.y);
                a2.x += q0.x; a2.y += q0.y; a2.z += q1.x; a2.w += q1.y;
                q0 = __half22float2(*(__half2*)&v3.x); q1 = __half22float2(*(__half2*)&v3.y);
                a3.x += q0.x; a3.y += q0.y; a3.z += q1.x; a3.w += q1.y;
            }
            for (; t < m; t++) {
                int sv0 = __shfl_sync(0xffffffffu, s, t);
                uint2 v0 = hrow[(size_t)sv0 * 32 + lane];
                float2 q0 = __half22float2(*(__half2*)&v0.x);
                float2 q1 = __half22float2(*(__half2*)&v0.y);
                a0.x += q0.x; a0.y += q0.y; a0.z += q1.x; a0.w += q1.y;
            }
        }
        float4 o;
        o.x = di * ((a0.x + a1.x) + (a2.x + a3.x)) + bb.x;
        o.y = di * ((a0.y + a1.y) + (a2.y + a3.y)) + bb.y;
        o.z = di * ((a0.z + a1.z) + (a2.z + a3.z)) + bb.z;
        o.w = di * ((a0.w + a1.w) + (a2.w + a3.w)) + bb.w;
        ((float4*)out)[(size_t)node * 32 + lane] = o;
        ssum.x += o.x; ssum.y += o.y; ssum.z += o.z; ssum.w += o.w;
        ssq.x += o.x * o.x; ssq.y += o.y * o.y; ssq.z += o.z * o.z; ssq.w += o.w * o.w;
    }

    atomicAdd(&sh_sum[lane * 4 + 0], ssum.x);
    atomicAdd(&sh_sum[lane * 4 + 1], ssum.y);
    atomicAdd(&sh_sum[lane * 4 + 2], ssum.z);
    atomicAdd(&sh_sum[lane * 4 + 3], ssum.w);
    atomicAdd(&sh_sq[lane * 4 + 0], ssq.x);
    atomicAdd(&sh_sq[lane * 4 + 1], ssq.y);
    atomicAdd(&sh_sq[lane * 4 + 2], ssq.z);
    atomicAdd(&sh_sq[lane * 4 + 3], ssq.w);
    __syncthreads();
    if (tid < 128) {
        atomicAdd(&g_stats[tid], sh_sum[tid]);
        atomicAdd(&g_stats[D + tid], sh_sq[tid]);
    }
}

// ---------------- BN + ReLU + residual -------------------------------------------
__global__ void k_final(const float* __restrict__ x, const float* __restrict__ gamma,
                        const float* __restrict__ beta, float* __restrict__ out, int N) {
    long long i = (long long)blockIdx.x * blockDim.x + threadIdx.x;
    long long total = (long long)N * 32;
    if (i >= total) return;
    int c4 = (int)(i & 31);
    float invN = 1.0f / (float)N;
    float4 v  = ((float4*)out)[i];
    float4 xv = ((const float4*)x)[i];
    float r[4] = {v.x, v.y, v.z, v.w};
    float xr[4] = {xv.x, xv.y, xv.z, xv.w};
#pragma unroll
    for (int c = 0; c < 4; c++) {
        int col = c4 * 4 + c;
        float mu  = g_stats[col] * invN;
        float var = g_stats[D + col] * invN - mu * mu;
        float inv = rsqrtf(var + BN_EPS);
        float y = __ldg(&gamma[col]) * (r[c] - mu) * inv + __ldg(&beta[col]);
        y = fmaxf(y, 0.0f);
        r[c] = y + xr[c];
    }
    ((float4*)out)[i] = make_float4(r[0], r[1], r[2], r[3]);
}

// ---------------- launcher: fork-join graph with GEMM on a side stream -----------
extern "C" void kernel_launch(void* const* d_in, const int* in_sizes, int n_in,
                              void* d_out, int out_size) {
    const float* x     = (const float*)d_in[0];
    const float* W     = (const float*)d_in[1];
    const float* bias  = (const float*)d_in[2];
    const float* gamma = (const float*)d_in[3];
    const float* beta  = (const float*)d_in[4];
    const void*  ei    = d_in[5];
    int N = in_sizes[0] / D;
    int E = in_sizes[5] / 2;
    float* out = (float*)d_out;

    cudaFuncSetAttribute(k_gemm_mma, cudaFuncAttributeMaxDynamicSharedMemorySize, SM_TOT);

    cudaStream_t s2;
    cudaStreamCreate(&s2);
    cudaEvent_t evFork, evJoin;
    cudaEventCreateWithFlags(&evFork, cudaEventDisableTiming);
    cudaEventCreateWithFlags(&evJoin, cudaEventDisableTiming);

    int nblk = (N + 1023) / 1024;
    k_init<<<(N + 255) / 256, 256>>>((const int*)ei, W, E, N);
    k_hist<<<(E + 255) / 256, 256>>>(ei, E);
    k_scan1<<<nblk, 1024>>>(N);

    // fork: GEMM depends only on init(W imgs) + scan1(dinv)
    cudaEventRecord(evFork, 0);
    cudaStreamWaitEvent(s2, evFork, 0);
    k_gemm_mma<<<(N + 63) / 64, 256, SM_TOT, s2>>>(x, N);
    cudaEventRecord(evJoin, s2);

    // main stream continues with CSR finalize concurrently
    k_scan3<<<nblk, 1024>>>(N);
    k_fill<<<(E + 255) / 256, 256>>>(ei, E);

    // join before aggregation (needs g_hh + g_csr)
    cudaStreamWaitEvent(0, evJoin, 0);
    int aggBlocks = 1036;                       // 7 blocks/SM * 148
    k_agg<<<aggBlocks, 256>>>(bias, out, N, aggBlocks * 8);
    k_final<<<(int)(((long long)N * 32 + 255) / 256), 256>>>(x, gamma, beta, out, N);

    cudaEventDestroy(evFork);
    cudaEventDestroy(evJoin);
    cudaStreamDestroy(s2);
}

// round 13
// speedup vs baseline: 1.1978x; 1.0862x over previous
#include <cuda_runtime.h>
#include <cuda_bf16.h>
#include <cuda_fp16.h>
#include <cstdint>

#define NNODES 100000
#define D 128
#define EMAX 2000000
#define BN_EPS 1e-5f

// ---------------- device scratch (no dynamic allocation allowed) ----------------
__device__ __half g_hh[(size_t)NNODES * D];   // h' = dinv * (x @ W^T), fp16 (25.6 MB)
__device__ float g_dinv[NNODES];              // 1/sqrt(deg)
__device__ int   g_counts[NNODES];            // in-degree (excluding self loop)
__device__ int   g_rowstart[NNODES];          // CSR row offsets
__device__ int   g_cursor[NNODES];            // fill cursors
__device__ int   g_csr[EMAX];                 // CSR column (src) indices
__device__ int   g_blocksums[128];            // scan partials (per scan1 block)
__device__ float g_stats[2 * D];              // sums / sumsq
__device__ int   g_is64;                      // edge_index dtype flag
// W as fp16, stored pre-swizzled (ldmatrix layout), 32KB
__device__ __align__(16) __half g_Wf16_img[16384];

// ---------------- warp-mma helpers (plain sm_80+ PTX, no 'a'-gated features) -----
__device__ __forceinline__ uint32_t smem_u32(const void* p) {
    uint32_t a;
    asm("{ .reg .u64 t; cvta.to.shared.u64 t, %1; cvt.u32.u64 %0, t; }" : "=r"(a) : "l"(p));
    return a;
}
__device__ __forceinline__ void ldm_x4(uint32_t& r0, uint32_t& r1, uint32_t& r2, uint32_t& r3,
                                       uint32_t addr) {
    asm volatile("ldmatrix.sync.aligned.m8n8.x4.shared.b16 {%0,%1,%2,%3}, [%4];"
                 : "=r"(r0), "=r"(r1), "=r"(r2), "=r"(r3) : "r"(addr));
}
__device__ __forceinline__ void mma_f16(float* c, const uint32_t* a, const uint32_t* b) {
    asm volatile(
        "mma.sync.aligned.m16n8k16.row.col.f32.f16.f16.f32 "
        "{%0,%1,%2,%3},{%4,%5,%6,%7},{%8,%9},{%0,%1,%2,%3};"
        : "+f"(c[0]), "+f"(c[1]), "+f"(c[2]), "+f"(c[3])
        : "r"(a[0]), "r"(a[1]), "r"(a[2]), "r"(a[3]), "r"(b[0]), "r"(b[1]));
}

// ---------------- edge index access (dtype detected at runtime) ----------------
__device__ __forceinline__ int edge_at(const void* ei, long long pos) {
    if (g_is64) return (int)((const long long*)ei)[pos];
    return ((const int*)ei)[pos];
}

// init: counters zero + dtype detect + stats zero + fused W fp16 image build
__global__ void k_init(const int* ei32, const float* __restrict__ W, int E, int N) {
    int i = blockIdx.x * blockDim.x + threadIdx.x;
    if (blockIdx.x == 0 && threadIdx.x < 32) {
        // int64 little-endian => odd int32 words of first 64 pairs are all zero
        int lane = threadIdx.x;
        int bad = 0;
        if (lane < E && ei32[2 * lane + 1] != 0) bad = 1;
        int k2 = lane + 32;
        if (k2 < E && k2 < 64 && ei32[2 * k2 + 1] != 0) bad = 1;
        unsigned m = __ballot_sync(0xffffffffu, bad);
        if (lane == 0) g_is64 = (m == 0u);
    }
    if (i < N) g_counts[i] = 0;
    if (i < 2 * D) g_stats[i] = 0.0f;
    if (i < 16384) {
        int r = i >> 7, k = i & 127;
        int kc = k >> 3;
        int idx = (r * 16 + (kc ^ (r & 7))) * 8 + (k & 7);
        g_Wf16_img[idx] = __float2half(W[i]);
    }
}

// hist: 1 edge/thread (proven form)
__global__ void k_hist(const void* ei, int E) {
    int e = blockIdx.x * blockDim.x + threadIdx.x;
    if (e >= E) return;
    int d = edge_at(ei, (long long)E + e);
    atomicAdd(&g_counts[d], 1);
}

// scan1: within-block exclusive scan; ALSO computes dinv (unblocks GEMM early)
__global__ void k_scan1(int N) {
    __shared__ int warp_off[32];
    int t = threadIdx.x;
    int gid = blockIdx.x * 1024 + t;
    int v = (gid < N) ? g_counts[gid] : 0;
    int lane = t & 31, wid = t >> 5;
    int s = v;
#pragma unroll
    for (int off = 1; off < 32; off <<= 1) {
        int n2 = __shfl_up_sync(0xffffffffu, s, off);
        if (lane >= off) s += n2;
    }
    if (lane == 31) warp_off[wid] = s;
    __syncthreads();
    if (wid == 0) {
        int ws = warp_off[lane];
        int ss = ws;
#pragma unroll
        for (int off = 1; off < 32; off <<= 1) {
            int n2 = __shfl_up_sync(0xffffffffu, ss, off);
            if (lane >= off) ss += n2;
        }
        warp_off[lane] = ss - ws;
        if (lane == 31) g_blocksums[blockIdx.x] = ss;
    }
    __syncthreads();
    if (gid < N) {
        g_rowstart[gid] = s + warp_off[wid] - v;
        g_dinv[gid]     = rsqrtf((float)v + 1.0f);
    }
}

// scan3: grid 1:1 with scan1 blocks; warp 0 computes the blocksum prefix once.
__global__ __launch_bounds__(1024) void k_scan3(int N) {
    __shared__ int s_off;
    int t = threadIdx.x;
    int b = blockIdx.x;
    if (t < 32) {
        int acc = 0;
#pragma unroll
        for (int j = 0; j < 4; j++) {
            int idx = t + j * 32;
            if (idx < b) acc += g_blocksums[idx];
        }
#pragma unroll
        for (int off = 16; off > 0; off >>= 1)
            acc += __shfl_down_sync(0xffffffffu, acc, off);
        if (t == 0) s_off = acc;
    }
    __syncthreads();
    int i = blockIdx.x * 1024 + t;
    if (i >= N) return;
    int rs = g_rowstart[i] + s_off;
    g_rowstart[i] = rs;
    g_cursor[i]   = rs;
}

// fill: 1 edge/thread (proven form)
__global__ void k_fill(const void* ei, int E) {
    int e = blockIdx.x * blockDim.x + threadIdx.x;
    if (e >= E) return;
    int s = edge_at(ei, e);
    int d = edge_at(ei, (long long)E + e);
    int pos = atomicAdd(&g_cursor[d], 1);
    if (pos < EMAX) g_csr[pos] = s;
}

// ------ GEMM: h' = dinv * (x_f16 @ W_f16^T) -> fp16, 64-row tiles, 4 CTAs/SM -----
#define SM_A  0
#define SM_B  16384
#define SM_TOT 49152

__global__ __launch_bounds__(256) void k_gemm_mma(const float* __restrict__ x, int N) {
    extern __shared__ char smem[];
    uint32_t sb = smem_u32(smem);
    int tid = threadIdx.x;
    int row0 = blockIdx.x * 64;

    // ---- copy pre-swizzled W fp16 image (2048 uint4) ----
    {
        const uint4* wf = (const uint4*)g_Wf16_img;
        uint4* bf = (uint4*)(smem + SM_B);
        for (int i = tid; i < 2048; i += 256) bf[i] = wf[i];
    }

    // ---- convert this tile's 64 x rows to fp16, swizzled ----
    {
        int r = tid >> 2;
        int q = tid & 3;
        int gr = row0 + r;
        char* A = smem + SM_A;
        if (gr < N) {
            const float4* xr = (const float4*)(x + (size_t)gr * 128) + q * 8;
#pragma unroll
            for (int j = 0; j < 4; j++) {
                float4 v0 = xr[2 * j];
                float4 v1 = xr[2 * j + 1];
                __half2 h0 = __floats2half2_rn(v0.x, v0.y);
                __half2 h1 = __floats2half2_rn(v0.z, v0.w);
                __half2 h2 = __floats2half2_rn(v1.x, v1.y);
                __half2 h3 = __floats2half2_rn(v1.z, v1.w);
                int kc = q * 4 + j;
                int off = (r * 16 + (kc ^ (r & 7))) * 16;
                *(uint4*)(A + off) = make_uint4(*(uint32_t*)&h0, *(uint32_t*)&h1,
                                                *(uint32_t*)&h2, *(uint32_t*)&h3);
            }
        } else {
            uint4 z = make_uint4(0, 0, 0, 0);
#pragma unroll
            for (int j = 0; j < 4; j++) {
                int kc = q * 4 + j;
                int off = (r * 16 + (kc ^ (r & 7))) * 16;
                *(uint4*)(smem + SM_A + off) = z;
            }
        }
    }
    __syncthreads();

    // ---- 8 warps: 2(m) x 4(n) -> warp tile 32(m) x 32(n) ----
    int warp = tid >> 5, lane = tid & 31;
    int wm = warp & 1, wn = warp >> 1;
    int m0 = wm * 32, n0 = wn * 32;
    int sub = lane >> 3, lrow = lane & 7;

    float acc[2][4][4];
#pragma unroll
    for (int mt = 0; mt < 2; mt++)
#pragma unroll
        for (int nt = 0; nt < 4; nt++)
#pragma unroll
            for (int q = 0; q < 4; q++) acc[mt][nt][q] = 0.f;

    int a_row_off = ((sub & 1) << 3) + lrow;
    int a_halfk   = sub >> 1;
    int b_row_off = ((sub & 2) << 2) + lrow;
    int b_halfk   = sub & 1;

#pragma unroll
    for (int ks = 0; ks < 8; ks++) {
        uint32_t a[2][4], b[4][2];
#pragma unroll
        for (int mt = 0; mt < 2; mt++) {
            int r = m0 + mt * 16 + a_row_off;
            int kc = 2 * ks + a_halfk;
            uint32_t addr = (uint32_t)((r * 16 + (kc ^ (r & 7))) * 16);
            ldm_x4(a[mt][0], a[mt][1], a[mt][2], a[mt][3], sb + SM_A + addr);
        }
#pragma unroll
        for (int np = 0; np < 2; np++) {
            int r = n0 + np * 16 + b_row_off;
            int kc = 2 * ks + b_halfk;
            uint32_t addr = (uint32_t)((r * 16 + (kc ^ (r & 7))) * 16);
            ldm_x4(b[2 * np][0], b[2 * np][1], b[2 * np + 1][0], b[2 * np + 1][1],
                   sb + SM_B + addr);
        }
#pragma unroll
        for (int mt = 0; mt < 2; mt++)
#pragma unroll
            for (int nt = 0; nt < 4; nt++)
                mma_f16(acc[mt][nt], a[mt], b[nt]);
    }

    // ---- epilogue: prescale rows by dinv, fp16 stores ----
    int qrow = lane >> 2, qcol = (lane & 3) * 2;
    __half2* h2p = (__half2*)g_hh;
#pragma unroll
    for (int mt = 0; mt < 2; mt++) {
        int r_lo = row0 + m0 + mt * 16 + qrow;
        int r_hi = r_lo + 8;
        float d_lo = (r_lo < N) ? g_dinv[r_lo] : 0.f;
        float d_hi = (r_hi < N) ? g_dinv[r_hi] : 0.f;
#pragma unroll
        for (int nt = 0; nt < 4; nt++) {
            int col = n0 + nt * 8 + qcol;
            if (r_lo < N)
                h2p[(size_t)r_lo * 64 + (col >> 1)] =
                    __floats2half2_rn(d_lo * acc[mt][nt][0], d_lo * acc[mt][nt][1]);
            if (r_hi < N)
                h2p[(size_t)r_hi * 64 + (col >> 1)] =
                    __floats2half2_rn(d_hi * acc[mt][nt][2], d_hi * acc[mt][nt][3]);
        }
    }
}

// ------- aggregation (grid-stride, warp per node) + fused BN statistics ----------
// proven form: 4 independent gathers in flight
__global__ __launch_bounds__(256) void k_agg(const float* __restrict__ bias,
                                             float* __restrict__ out, int N, int totalWarps) {
    __shared__ float sh_sum[128];
    __shared__ float sh_sq[128];
    int tid = threadIdx.x;
    int lane = tid & 31;
    if (tid < 128) { sh_sum[tid] = 0.f; sh_sq[tid] = 0.f; }
    __syncthreads();

    int gwarp = blockIdx.x * 8 + (tid >> 5);
    const uint2* hrow = (const uint2*)g_hh;   // 32 uint2 per 128-half row
    float4 bb = ((const float4*)bias)[lane];
    float4 ssum = make_float4(0.f, 0.f, 0.f, 0.f);
    float4 ssq  = make_float4(0.f, 0.f, 0.f, 0.f);

    for (int node = gwarp; node < N; node += totalWarps) {
        int   base = g_rowstart[node];
        int   cnt  = g_counts[node];
        float di   = g_dinv[node];

        float4 a0, a1, a2, a3;
        {
            uint2 v = hrow[(size_t)node * 32 + lane];
            float2 p0 = __half22float2(*(__half2*)&v.x);
            float2 p1 = __half22float2(*(__half2*)&v.y);
            a0 = make_float4(p0.x, p0.y, p1.x, p1.y);
        }
        a1 = make_float4(0.f, 0.f, 0.f, 0.f);
        a2 = make_float4(0.f, 0.f, 0.f, 0.f);
        a3 = make_float4(0.f, 0.f, 0.f, 0.f);

        for (int j0 = 0; j0 < cnt; j0 += 32) {
            int myj = j0 + lane;
            int s = (myj < cnt) ? g_csr[base + myj] : 0;
            int m = min(32, cnt - j0);
            int t = 0;
            for (; t + 4 <= m; t += 4) {
                int sv0 = __shfl_sync(0xffffffffu, s, t);
                int sv1 = __shfl_sync(0xffffffffu, s, t + 1);
                int sv2 = __shfl_sync(0xffffffffu, s, t + 2);
                int sv3 = __shfl_sync(0xffffffffu, s, t + 3);
                uint2 v0 = hrow[(size_t)sv0 * 32 + lane];
                uint2 v1 = hrow[(size_t)sv1 * 32 + lane];
                uint2 v2 = hrow[(size_t)sv2 * 32 + lane];
                uint2 v3 = hrow[(size_t)sv3 * 32 + lane];
                float2 q0, q1;
                q0 = __half22float2(*(__half2*)&v0.x); q1 = __half22float2(*(__half2*)&v0.y);
                a0.x += q0.x; a0.y += q0.y; a0.z += q1.x; a0.w += q1.y;
                q0 = __half22float2(*(__half2*)&v1.x); q1 = __half22float2(*(__half2*)&v1.y);
                a1.x += q0.x; a1.y += q0.y; a1.z += q1.x; a1.w += q1.y;
                q0 = __half22float2(*(__half2*)&v2.x); q1 = __half22float2(*(__half2*)&v2.y);
                a2.x += q0.x; a2.y += q0.y; a2.z += q1.x; a2.w += q1.y;
                q0 = __half22float2(*(__half2*)&v3.x); q1 = __half22float2(*(__half2*)&v3.y);
                a3.x += q0.x; a3.y += q0.y; a3.z += q1.x; a3.w += q1.y;
            }
            for (; t < m; t++) {
                int sv0 = __shfl_sync(0xffffffffu, s, t);
                uint2 v0 = hrow[(size_t)sv0 * 32 + lane];
                float2 q0 = __half22float2(*(__half2*)&v0.x);
                float2 q1 = __half22float2(*(__half2*)&v0.y);
                a0.x += q0.x; a0.y += q0.y; a0.z += q1.x; a0.w += q1.y;
            }
        }
        float4 o;
        o.x = di * ((a0.x + a1.x) + (a2.x + a3.x)) + bb.x;
        o.y = di * ((a0.y + a1.y) + (a2.y + a3.y)) + bb.y;
        o.z = di * ((a0.z + a1.z) + (a2.z + a3.z)) + bb.z;
        o.w = di * ((a0.w + a1.w) + (a2.w + a3.w)) + bb.w;
        ((float4*)out)[(size_t)node * 32 + lane] = o;
        ssum.x += o.x; ssum.y += o.y; ssum.z += o.z; ssum.w += o.w;
        ssq.x += o.x * o.x; ssq.y += o.y * o.y; ssq.z += o.z * o.z; ssq.w += o.w * o.w;
    }

    atomicAdd(&sh_sum[lane * 4 + 0], ssum.x);
    atomicAdd(&sh_sum[lane * 4 + 1], ssum.y);
    atomicAdd(&sh_sum[lane * 4 + 2], ssum.z);
    atomicAdd(&sh_sum[lane * 4 + 3], ssum.w);
    atomicAdd(&sh_sq[lane * 4 + 0], ssq.x);
    atomicAdd(&sh_sq[lane * 4 + 1], ssq.y);
    atomicAdd(&sh_sq[lane * 4 + 2], ssq.z);
    atomicAdd(&sh_sq[lane * 4 + 3], ssq.w);
    __syncthreads();
    if (tid < 128) {
        atomicAdd(&g_stats[tid], sh_sum[tid]);
        atomicAdd(&g_stats[D + tid], sh_sq[tid]);
    }
}

// ---------------- BN + ReLU + residual -------------------------------------------
__global__ void k_final(const float* __restrict__ x, const float* __restrict__ gamma,
                        const float* __restrict__ beta, float* __restrict__ out, int N) {
    long long i = (long long)blockIdx.x * blockDim.x + threadIdx.x;
    long long total = (long long)N * 32;
    if (i >= total) return;
    int c4 = (int)(i & 31);
    float invN = 1.0f / (float)N;
    float4 v  = ((float4*)out)[i];
    float4 xv = ((const float4*)x)[i];
    float r[4] = {v.x, v.y, v.z, v.w};
    float xr[4] = {xv.x, xv.y, xv.z, xv.w};
#pragma unroll
    for (int c = 0; c < 4; c++) {
        int col = c4 * 4 + c;
        float mu  = g_stats[col] * invN;
        float var = g_stats[D + col] * invN - mu * mu;
        float inv = rsqrtf(var + BN_EPS);
        float y = __ldg(&gamma[col]) * (r[c] - mu) * inv + __ldg(&beta[col]);
        y = fmaxf(y, 0.0f);
        r[c] = y + xr[c];
    }
    ((float4*)out)[i] = make_float4(r[0], r[1], r[2], r[3]);
}

// ---------------- launcher: fork-join graph with GEMM on a side stream -----------
extern "C" void kernel_launch(void* const* d_in, const int* in_sizes, int n_in,
                              void* d_out, int out_size) {
    const float* x     = (const float*)d_in[0];
    const float* W     = (const float*)d_in[1];
    const float* bias  = (const float*)d_in[2];
    const float* gamma = (const float*)d_in[3];
    const float* beta  = (const float*)d_in[4];
    const void*  ei    = d_in[5];
    int N = in_sizes[0] / D;
    int E = in_sizes[5] / 2;
    float* out = (float*)d_out;

    cudaFuncSetAttribute(k_gemm_mma, cudaFuncAttributeMaxDynamicSharedMemorySize, SM_TOT);

    cudaStream_t s2;
    cudaStreamCreate(&s2);
    cudaEvent_t evFork, evJoin;
    cudaEventCreateWithFlags(&evFork, cudaEventDisableTiming);
    cudaEventCreateWithFlags(&evJoin, cudaEventDisableTiming);

    int nblk = (N + 1023) / 1024;
    k_init<<<(N + 255) / 256, 256>>>((const int*)ei, W, E, N);
    k_hist<<<(E + 255) / 256, 256>>>(ei, E);
    k_scan1<<<nblk, 1024>>>(N);

    // fork: GEMM depends only on init(W img) + scan1(dinv)
    cudaEventRecord(evFork, 0);
    cudaStreamWaitEvent(s2, evFork, 0);
    k_gemm_mma<<<(N + 63) / 64, 256, SM_TOT, s2>>>(x, N);
    cudaEventRecord(evJoin, s2);

    // main stream continues with CSR finalize concurrently
    k_scan3<<<nblk, 1024>>>(N);
    k_fill<<<(E + 255) / 256, 256>>>(ei, E);

    // join before aggregation (needs g_hh + g_csr)
    cudaStreamWaitEvent(0, evJoin, 0);
    int aggBlocks = 1036;                       // 7 blocks/SM * 148
    k_agg<<<aggBlocks, 256>>>(bias, out, N, aggBlocks * 8);
    k_final<<<(int)(((long long)N * 32 + 255) / 256), 256>>>(x, gamma, beta, out, N);

    cudaEventDestroy(evFork);
    cudaEventDestroy(evJoin);
    cudaStreamDestroy(s2);
}

// round 14
// speedup vs baseline: 1.2247x; 1.0225x over previous
#include <cuda_runtime.h>
#include <cuda_bf16.h>
#include <cuda_fp16.h>
#include <cstdint>

#define NNODES 100000
#define D 128
#define EMAX 2000000
#define BN_EPS 1e-5f

// ---------------- device scratch (no dynamic allocation allowed) ----------------
__device__ __half g_hh[(size_t)NNODES * D];   // h' = dinv * (x @ W^T), fp16 (25.6 MB)
__device__ float g_dinv[NNODES];              // 1/sqrt(deg)
__device__ int   g_counts[NNODES];            // in-degree (excluding self loop)
__device__ int   g_rowstart[NNODES];          // CSR row offsets
__device__ int   g_cursor[NNODES];            // fill cursors
__device__ int   g_csr[EMAX];                 // CSR column (src) indices
__device__ int   g_blocksums[128];            // scan partials (per scan1 block)
__device__ float g_stats[2 * D];              // sums / sumsq
__device__ int   g_is64;                      // edge_index dtype flag
// W as fp16, stored pre-swizzled (ldmatrix layout), 32KB
__device__ __align__(16) __half g_Wf16_img[16384];

// ---------------- warp-mma helpers (plain sm_80+ PTX, no 'a'-gated features) -----
__device__ __forceinline__ uint32_t smem_u32(const void* p) {
    uint32_t a;
    asm("{ .reg .u64 t; cvta.to.shared.u64 t, %1; cvt.u32.u64 %0, t; }" : "=r"(a) : "l"(p));
    return a;
}
__device__ __forceinline__ void ldm_x4(uint32_t& r0, uint32_t& r1, uint32_t& r2, uint32_t& r3,
                                       uint32_t addr) {
    asm volatile("ldmatrix.sync.aligned.m8n8.x4.shared.b16 {%0,%1,%2,%3}, [%4];"
                 : "=r"(r0), "=r"(r1), "=r"(r2), "=r"(r3) : "r"(addr));
}
__device__ __forceinline__ void mma_f16(float* c, const uint32_t* a, const uint32_t* b) {
    asm volatile(
        "mma.sync.aligned.m16n8k16.row.col.f32.f16.f16.f32 "
        "{%0,%1,%2,%3},{%4,%5,%6,%7},{%8,%9},{%0,%1,%2,%3};"
        : "+f"(c[0]), "+f"(c[1]), "+f"(c[2]), "+f"(c[3])
        : "r"(a[0]), "r"(a[1]), "r"(a[2]), "r"(a[3]), "r"(b[0]), "r"(b[1]));
}

// ---------------- edge index access (dtype detected at runtime) ----------------
__device__ __forceinline__ int edge_at(const void* ei, long long pos) {
    if (g_is64) return (int)((const long long*)ei)[pos];
    return ((const int*)ei)[pos];
}

// init: counters zero + dtype detect + stats zero + fused W fp16 image build
__global__ void k_init(const int* ei32, const float* __restrict__ W, int E, int N) {
    int i = blockIdx.x * blockDim.x + threadIdx.x;
    if (blockIdx.x == 0 && threadIdx.x < 32) {
        // int64 little-endian => odd int32 words of first 64 pairs are all zero
        int lane = threadIdx.x;
        int bad = 0;
        if (lane < E && ei32[2 * lane + 1] != 0) bad = 1;
        int k2 = lane + 32;
        if (k2 < E && k2 < 64 && ei32[2 * k2 + 1] != 0) bad = 1;
        unsigned m = __ballot_sync(0xffffffffu, bad);
        if (lane == 0) g_is64 = (m == 0u);
    }
    if (i < N) g_counts[i] = 0;
    if (i < 2 * D) g_stats[i] = 0.0f;
    if (i < 16384) {
        int r = i >> 7, k = i & 127;
        int kc = k >> 3;
        int idx = (r * 16 + (kc ^ (r & 7))) * 8 + (k & 7);
        g_Wf16_img[idx] = __float2half(W[i]);
    }
}

// hist: 1 edge/thread (proven form)
__global__ void k_hist(const void* ei, int E) {
    int e = blockIdx.x * blockDim.x + threadIdx.x;
    if (e >= E) return;
    int d = edge_at(ei, (long long)E + e);
    atomicAdd(&g_counts[d], 1);
}

// scan1: within-block exclusive scan; ALSO computes dinv (unblocks GEMM early)
__global__ void k_scan1(int N) {
    __shared__ int warp_off[32];
    int t = threadIdx.x;
    int gid = blockIdx.x * 1024 + t;
    int v = (gid < N) ? g_counts[gid] : 0;
    int lane = t & 31, wid = t >> 5;
    int s = v;
#pragma unroll
    for (int off = 1; off < 32; off <<= 1) {
        int n2 = __shfl_up_sync(0xffffffffu, s, off);
        if (lane >= off) s += n2;
    }
    if (lane == 31) warp_off[wid] = s;
    __syncthreads();
    if (wid == 0) {
        int ws = warp_off[lane];
        int ss = ws;
#pragma unroll
        for (int off = 1; off < 32; off <<= 1) {
            int n2 = __shfl_up_sync(0xffffffffu, ss, off);
            if (lane >= off) ss += n2;
        }
        warp_off[lane] = ss - ws;
        if (lane == 31) g_blocksums[blockIdx.x] = ss;
    }
    __syncthreads();
    if (gid < N) {
        g_rowstart[gid] = s + warp_off[wid] - v;
        g_dinv[gid]     = rsqrtf((float)v + 1.0f);
    }
}

// scan3: grid 1:1 with scan1 blocks; warp 0 computes the blocksum prefix once.
__global__ __launch_bounds__(1024) void k_scan3(int N) {
    __shared__ int s_off;
    int t = threadIdx.x;
    int b = blockIdx.x;
    if (t < 32) {
        int acc = 0;
#pragma unroll
        for (int j = 0; j < 4; j++) {
            int idx = t + j * 32;
            if (idx < b) acc += g_blocksums[idx];
        }
#pragma unroll
        for (int off = 16; off > 0; off >>= 1)
            acc += __shfl_down_sync(0xffffffffu, acc, off);
        if (t == 0) s_off = acc;
    }
    __syncthreads();
    int i = blockIdx.x * 1024 + t;
    if (i >= N) return;
    int rs = g_rowstart[i] + s_off;
    g_rowstart[i] = rs;
    g_cursor[i]   = rs;
}

// fill: 1 edge/thread (proven form)
__global__ void k_fill(const void* ei, int E) {
    int e = blockIdx.x * blockDim.x + threadIdx.x;
    if (e >= E) return;
    int s = edge_at(ei, e);
    int d = edge_at(ei, (long long)E + e);
    int pos = atomicAdd(&g_cursor[d], 1);
    if (pos < EMAX) g_csr[pos] = s;
}

// ---- GEMM: h' = dinv * (x_f16 @ W_f16^T) -> fp16, 128-row tiles, 3 CTAs/SM ------
#define SM_A  0
#define SM_B  32768
#define SM_TOT 65536

__global__ __launch_bounds__(256) void k_gemm_mma(const float* __restrict__ x, int N) {
    extern __shared__ char smem[];
    uint32_t sb = smem_u32(smem);
    int tid = threadIdx.x;
    int row0 = blockIdx.x * 128;

    // ---- copy pre-swizzled W fp16 image (2048 uint4) ----
    {
        const uint4* wf = (const uint4*)g_Wf16_img;
        uint4* bf = (uint4*)(smem + SM_B);
        for (int i = tid; i < 2048; i += 256) bf[i] = wf[i];
    }

    // ---- convert this tile's 128 x rows to fp16, swizzled (2 threads/row) ----
    {
        int r  = tid >> 1;          // 0..127
        int hf = tid & 1;           // half-row: kc = hf*8 + j
        int gr = row0 + r;
        char* A = smem + SM_A;
        if (gr < N) {
            const float4* xr = (const float4*)(x + (size_t)gr * 128) + hf * 16;
#pragma unroll
            for (int j = 0; j < 8; j++) {
                float4 v0 = xr[2 * j];
                float4 v1 = xr[2 * j + 1];
                __half2 h0 = __floats2half2_rn(v0.x, v0.y);
                __half2 h1 = __floats2half2_rn(v0.z, v0.w);
                __half2 h2 = __floats2half2_rn(v1.x, v1.y);
                __half2 h3 = __floats2half2_rn(v1.z, v1.w);
                int kc = hf * 8 + j;
                int off = (r * 16 + (kc ^ (r & 7))) * 16;
                *(uint4*)(A + off) = make_uint4(*(uint32_t*)&h0, *(uint32_t*)&h1,
                                                *(uint32_t*)&h2, *(uint32_t*)&h3);
            }
        } else {
            uint4 z = make_uint4(0, 0, 0, 0);
#pragma unroll
            for (int j = 0; j < 8; j++) {
                int kc = hf * 8 + j;
                int off = (r * 16 + (kc ^ (r & 7))) * 16;
                *(uint4*)(smem + SM_A + off) = z;
            }
        }
    }
    __syncthreads();

    // ---- 8 warps: 4(m) x 2(n) -> warp tile 32(m) x 64(n) ----
    int warp = tid >> 5, lane = tid & 31;
    int wm = warp & 3, wn = warp >> 2;
    int m0 = wm * 32, n0 = wn * 64;
    int sub = lane >> 3, lrow = lane & 7;

    float acc[2][8][4];
#pragma unroll
    for (int mt = 0; mt < 2; mt++)
#pragma unroll
        for (int nt = 0; nt < 8; nt++)
#pragma unroll
            for (int q = 0; q < 4; q++) acc[mt][nt][q] = 0.f;

    int a_row_off = ((sub & 1) << 3) + lrow;
    int a_halfk   = sub >> 1;
    int b_row_off = ((sub & 2) << 2) + lrow;
    int b_halfk   = sub & 1;

#pragma unroll
    for (int ks = 0; ks < 8; ks++) {
        uint32_t a[2][4], b[8][2];
#pragma unroll
        for (int mt = 0; mt < 2; mt++) {
            int r = m0 + mt * 16 + a_row_off;
            int kc = 2 * ks + a_halfk;
            uint32_t addr = (uint32_t)((r * 16 + (kc ^ (r & 7))) * 16);
            ldm_x4(a[mt][0], a[mt][1], a[mt][2], a[mt][3], sb + SM_A + addr);
        }
#pragma unroll
        for (int np = 0; np < 4; np++) {
            int r = n0 + np * 16 + b_row_off;
            int kc = 2 * ks + b_halfk;
            uint32_t addr = (uint32_t)((r * 16 + (kc ^ (r & 7))) * 16);
            ldm_x4(b[2 * np][0], b[2 * np][1], b[2 * np + 1][0], b[2 * np + 1][1],
                   sb + SM_B + addr);
        }
#pragma unroll
        for (int mt = 0; mt < 2; mt++)
#pragma unroll
            for (int nt = 0; nt < 8; nt++)
                mma_f16(acc[mt][nt], a[mt], b[nt]);
    }

    // ---- epilogue: prescale rows by dinv, fp16 stores ----
    int qrow = lane >> 2, qcol = (lane & 3) * 2;
    __half2* h2p = (__half2*)g_hh;
#pragma unroll
    for (int mt = 0; mt < 2; mt++) {
        int r_lo = row0 + m0 + mt * 16 + qrow;
        int r_hi = r_lo + 8;
        float d_lo = (r_lo < N) ? g_dinv[r_lo] : 0.f;
        float d_hi = (r_hi < N) ? g_dinv[r_hi] : 0.f;
#pragma unroll
        for (int nt = 0; nt < 8; nt++) {
            int col = n0 + nt * 8 + qcol;
            if (r_lo < N)
                h2p[(size_t)r_lo * 64 + (col >> 1)] =
                    __floats2half2_rn(d_lo * acc[mt][nt][0], d_lo * acc[mt][nt][1]);
            if (r_hi < N)
                h2p[(size_t)r_hi * 64 + (col >> 1)] =
                    __floats2half2_rn(d_hi * acc[mt][nt][2], d_hi * acc[mt][nt][3]);
        }
    }
}

// ------- aggregation (grid-stride, warp per node) + fused BN statistics ----------
// proven form: 4 independent gathers in flight
__global__ __launch_bounds__(256) void k_agg(const float* __restrict__ bias,
                                             float* __restrict__ out, int N, int totalWarps) {
    __shared__ float sh_sum[128];
    __shared__ float sh_sq[128];
    int tid = threadIdx.x;
    int lane = tid & 31;
    if (tid < 128) { sh_sum[tid] = 0.f; sh_sq[tid] = 0.f; }
    __syncthreads();

    int gwarp = blockIdx.x * 8 + (tid >> 5);
    const uint2* hrow = (const uint2*)g_hh;   // 32 uint2 per 128-half row
    float4 bb = ((const float4*)bias)[lane];
    float4 ssum = make_float4(0.f, 0.f, 0.f, 0.f);
    float4 ssq  = make_float4(0.f, 0.f, 0.f, 0.f);

    for (int node = gwarp; node < N; node += totalWarps) {
        int   base = g_rowstart[node];
        int   cnt  = g_counts[node];
        float di   = g_dinv[node];

        float4 a0, a1, a2, a3;
        {
            uint2 v = hrow[(size_t)node * 32 + lane];
            float2 p0 = __half22float2(*(__half2*)&v.x);
            float2 p1 = __half22float2(*(__half2*)&v.y);
            a0 = make_float4(p0.x, p0.y, p1.x, p1.y);
        }
        a1 = make_float4(0.f, 0.f, 0.f, 0.f);
        a2 = make_float4(0.f, 0.f, 0.f, 0.f);
        a3 = make_float4(0.f, 0.f, 0.f, 0.f);

        for (int j0 = 0; j0 < cnt; j0 += 32) {
            int myj = j0 + lane;
            int s = (myj < cnt) ? g_csr[base + myj] : 0;
            int m = min(32, cnt - j0);
            int t = 0;
            for (; t + 4 <= m; t += 4) {
                int sv0 = __shfl_sync(0xffffffffu, s, t);
                int sv1 = __shfl_sync(0xffffffffu, s, t + 1);
                int sv2 = __shfl_sync(0xffffffffu, s, t + 2);
                int sv3 = __shfl_sync(0xffffffffu, s, t + 3);
                uint2 v0 = hrow[(size_t)sv0 * 32 + lane];
                uint2 v1 = hrow[(size_t)sv1 * 32 + lane];
                uint2 v2 = hrow[(size_t)sv2 * 32 + lane];
                uint2 v3 = hrow[(size_t)sv3 * 32 + lane];
                float2 q0, q1;
                q0 = __half22float2(*(__half2*)&v0.x); q1 = __half22float2(*(__half2*)&v0.y);
                a0.x += q0.x; a0.y += q0.y; a0.z += q1.x; a0.w += q1.y;
                q0 = __half22float2(*(__half2*)&v1.x); q1 = __half22float2(*(__half2*)&v1.y);
                a1.x += q0.x; a1.y += q0.y; a1.z += q1.x; a1.w += q1.y;
                q0 = __half22float2(*(__half2*)&v2.x); q1 = __half22float2(*(__half2*)&v2.y);
                a2.x += q0.x; a2.y += q0.y; a2.z += q1.x; a2.w += q1.y;
                q0 = __half22float2(*(__half2*)&v3.x); q1 = __half22float2(*(__half2*)&v3.y);
                a3.x += q0.x; a3.y += q0.y; a3.z += q1.x; a3.w += q1.y;
            }
            for (; t < m; t++) {
                int sv0 = __shfl_sync(0xffffffffu, s, t);
                uint2 v0 = hrow[(size_t)sv0 * 32 + lane];
                float2 q0 = __half22float2(*(__half2*)&v0.x);
                float2 q1 = __half22float2(*(__half2*)&v0.y);
                a0.x += q0.x; a0.y += q0.y; a0.z += q1.x; a0.w += q1.y;
            }
        }
        float4 o;
        o.x = di * ((a0.x + a1.x) + (a2.x + a3.x)) + bb.x;
        o.y = di * ((a0.y + a1.y) + (a2.y + a3.y)) + bb.y;
        o.z = di * ((a0.z + a1.z) + (a2.z + a3.z)) + bb.z;
        o.w = di * ((a0.w + a1.w) + (a2.w + a3.w)) + bb.w;
        ((float4*)out)[(size_t)node * 32 + lane] = o;
        ssum.x += o.x; ssum.y += o.y; ssum.z += o.z; ssum.w += o.w;
        ssq.x += o.x * o.x; ssq.y += o.y * o.y; ssq.z += o.z * o.z; ssq.w += o.w * o.w;
    }

    atomicAdd(&sh_sum[lane * 4 + 0], ssum.x);
    atomicAdd(&sh_sum[lane * 4 + 1], ssum.y);
    atomicAdd(&sh_sum[lane * 4 + 2], ssum.z);
    atomicAdd(&sh_sum[lane * 4 + 3], ssum.w);
    atomicAdd(&sh_sq[lane * 4 + 0], ssq.x);
    atomicAdd(&sh_sq[lane * 4 + 1], ssq.y);
    atomicAdd(&sh_sq[lane * 4 + 2], ssq.z);
    atomicAdd(&sh_sq[lane * 4 + 3], ssq.w);
    __syncthreads();
    if (tid < 128) {
        atomicAdd(&g_stats[tid], sh_sum[tid]);
        atomicAdd(&g_stats[D + tid], sh_sq[tid]);
    }
}

// ---------------- BN + ReLU + residual -------------------------------------------
__global__ void k_final(const float* __restrict__ x, const float* __restrict__ gamma,
                        const float* __restrict__ beta, float* __restrict__ out, int N) {
    long long i = (long long)blockIdx.x * blockDim.x + threadIdx.x;
    long long total = (long long)N * 32;
    if (i >= total) return;
    int c4 = (int)(i & 31);
    float invN = 1.0f / (float)N;
    float4 v  = ((float4*)out)[i];
    float4 xv = ((const float4*)x)[i];
    float r[4] = {v.x, v.y, v.z, v.w};
    float xr[4] = {xv.x, xv.y, xv.z, xv.w};
#pragma unroll
    for (int c = 0; c < 4; c++) {
        int col = c4 * 4 + c;
        float mu  = g_stats[col] * invN;
        float var = g_stats[D + col] * invN - mu * mu;
        float inv = rsqrtf(var + BN_EPS);
        float y = __ldg(&gamma[col]) * (r[c] - mu) * inv + __ldg(&beta[col]);
        y = fmaxf(y, 0.0f);
        r[c] = y + xr[c];
    }
    ((float4*)out)[i] = make_float4(r[0], r[1], r[2], r[3]);
}

// ---------------- launcher: fork-join graph with GEMM on a side stream -----------
extern "C" void kernel_launch(void* const* d_in, const int* in_sizes, int n_in,
                              void* d_out, int out_size) {
    const float* x     = (const float*)d_in[0];
    const float* W     = (const float*)d_in[1];
    const float* bias  = (const float*)d_in[2];
    const float* gamma = (const float*)d_in[3];
    const float* beta  = (const float*)d_in[4];
    const void*  ei    = d_in[5];
    int N = in_sizes[0] / D;
    int E = in_sizes[5] / 2;
    float* out = (float*)d_out;

    cudaFuncSetAttribute(k_gemm_mma, cudaFuncAttributeMaxDynamicSharedMemorySize, SM_TOT);

    cudaStream_t s2;
    cudaStreamCreate(&s2);
    cudaEvent_t evFork, evJoin;
    cudaEventCreateWithFlags(&evFork, cudaEventDisableTiming);
    cudaEventCreateWithFlags(&evJoin, cudaEventDisableTiming);

    int nblk = (N + 1023) / 1024;
    k_init<<<(N + 255) / 256, 256>>>((const int*)ei, W, E, N);
    k_hist<<<(E + 255) / 256, 256>>>(ei, E);
    k_scan1<<<nblk, 1024>>>(N);

    // fork: GEMM depends only on init(W img) + scan1(dinv)
    cudaEventRecord(evFork, 0);
    cudaStreamWaitEvent(s2, evFork, 0);
    k_gemm_mma<<<(N + 127) / 128, 256, SM_TOT, s2>>>(x, N);
    cudaEventRecord(evJoin, s2);

    // main stream continues with CSR finalize concurrently
    k_scan3<<<nblk, 1024>>>(N);
    k_fill<<<(E + 255) / 256, 256>>>(ei, E);

    // join before aggregation (needs g_hh + g_csr)
    cudaStreamWaitEvent(0, evJoin, 0);
    int aggBlocks = 1036;                       // 7 blocks/SM * 148
    k_agg<<<aggBlocks, 256>>>(bias, out, N, aggBlocks * 8);
    k_final<<<(int)(((long long)N * 32 + 255) / 256), 256>>>(x, gamma, beta, out, N);

    cudaEventDestroy(evFork);
    cudaEventDestroy(evJoin);
    cudaStreamDestroy(s2);
}

// round 15
// speedup vs baseline: 1.2646x; 1.0326x over previous
#include <cuda_runtime.h>
#include <cuda_fp16.h>
#include <cstdint>

#define NNODES 100000
#define D 128
#define EMAX 2000000
#define BN_EPS 1e-5f

// ---------------- device scratch (no dynamic allocation allowed) ----------------
__device__ __half g_hh[(size_t)NNODES * D];   // h' = dinv * (x @ W^T), fp16 (25.6 MB)
__device__ float g_dinv[NNODES];              // 1/sqrt(deg)
__device__ int   g_counts[NNODES];            // in-degree (excluding self loop)
__device__ int   g_rowstart[NNODES];          // CSR row offsets
__device__ int   g_cursor[NNODES];            // fill cursors
__device__ int   g_csr[EMAX];                 // CSR column (src) indices
__device__ int   g_blocksums[128];            // scan partials (per scan1 block)
__device__ float g_stats[2 * D];              // sums / sumsq
__device__ int   g_is64;                      // edge_index dtype flag
// W as fp16, stored pre-swizzled (ldmatrix layout), 32KB
__device__ __align__(16) __half g_Wf16_img[16384];

// ---------------- warp-mma helpers (plain sm_80+ PTX, no 'a'-gated features) -----
__device__ __forceinline__ uint32_t smem_u32(const void* p) {
    uint32_t a;
    asm("{ .reg .u64 t; cvta.to.shared.u64 t, %1; cvt.u32.u64 %0, t; }" : "=r"(a) : "l"(p));
    return a;
}
__device__ __forceinline__ void ldm_x4(uint32_t& r0, uint32_t& r1, uint32_t& r2, uint32_t& r3,
                                       uint32_t addr) {
    asm volatile("ldmatrix.sync.aligned.m8n8.x4.shared.b16 {%0,%1,%2,%3}, [%4];"
                 : "=r"(r0), "=r"(r1), "=r"(r2), "=r"(r3) : "r"(addr));
}
__device__ __forceinline__ void mma_f16(float* c, const uint32_t* a, const uint32_t* b) {
    asm volatile(
        "mma.sync.aligned.m16n8k16.row.col.f32.f16.f16.f32 "
        "{%0,%1,%2,%3},{%4,%5,%6,%7},{%8,%9},{%0,%1,%2,%3};"
        : "+f"(c[0]), "+f"(c[1]), "+f"(c[2]), "+f"(c[3])
        : "r"(a[0]), "r"(a[1]), "r"(a[2]), "r"(a[3]), "r"(b[0]), "r"(b[1]));
}
__device__ __forceinline__ void cpasync16(uint32_t dst, const void* src) {
    asm volatile("cp.async.cg.shared.global [%0], [%1], 16;" :: "r"(dst), "l"(src));
}

// ---------------- edge index access (dtype detected at runtime) ----------------
__device__ __forceinline__ int edge_at(const void* ei, long long pos) {
    if (g_is64) return (int)((const long long*)ei)[pos];
    return ((const int*)ei)[pos];
}

// init: counters zero + dtype detect + stats zero + fused W fp16 image build
__global__ void k_init(const int* ei32, const float* __restrict__ W, int E, int N) {
    int i = blockIdx.x * blockDim.x + threadIdx.x;
    if (blockIdx.x == 0 && threadIdx.x < 32) {
        // int64 little-endian => odd int32 words of first 64 pairs are all zero
        int lane = threadIdx.x;
        int bad = 0;
        if (lane < E && ei32[2 * lane + 1] != 0) bad = 1;
        int k2 = lane + 32;
        if (k2 < E && k2 < 64 && ei32[2 * k2 + 1] != 0) bad = 1;
        unsigned m = __ballot_sync(0xffffffffu, bad);
        if (lane == 0) g_is64 = (m == 0u);
    }
    if (i < N) g_counts[i] = 0;
    if (i < 2 * D) g_stats[i] = 0.0f;
    if (i < 16384) {
        int r = i >> 7, k = i & 127;
        int kc = k >> 3;
        int idx = (r * 16 + (kc ^ (r & 7))) * 8 + (k & 7);
        g_Wf16_img[idx] = __float2half(W[i]);
    }
}

// hist: 1 edge/thread (proven form)
__global__ void k_hist(const void* ei, int E) {
    int e = blockIdx.x * blockDim.x + threadIdx.x;
    if (e >= E) return;
    int d = edge_at(ei, (long long)E + e);
    atomicAdd(&g_counts[d], 1);
}

// scan1: within-block exclusive scan; ALSO computes dinv (unblocks GEMM early)
__global__ void k_scan1(int N) {
    __shared__ int warp_off[32];
    int t = threadIdx.x;
    int gid = blockIdx.x * 1024 + t;
    int v = (gid < N) ? g_counts[gid] : 0;
    int lane = t & 31, wid = t >> 5;
    int s = v;
#pragma unroll
    for (int off = 1; off < 32; off <<= 1) {
        int n2 = __shfl_up_sync(0xffffffffu, s, off);
        if (lane >= off) s += n2;
    }
    if (lane == 31) warp_off[wid] = s;
    __syncthreads();
    if (wid == 0) {
        int ws = warp_off[lane];
        int ss = ws;
#pragma unroll
        for (int off = 1; off < 32; off <<= 1) {
            int n2 = __shfl_up_sync(0xffffffffu, ss, off);
            if (lane >= off) ss += n2;
        }
        warp_off[lane] = ss - ws;
        if (lane == 31) g_blocksums[blockIdx.x] = ss;
    }
    __syncthreads();
    if (gid < N) {
        g_rowstart[gid] = s + warp_off[wid] - v;
        g_dinv[gid]     = rsqrtf((float)v + 1.0f);
    }
}

// scan3: grid 1:1 with scan1 blocks; warp 0 computes the blocksum prefix once.
__global__ __launch_bounds__(1024) void k_scan3(int N) {
    __shared__ int s_off;
    int t = threadIdx.x;
    int b = blockIdx.x;
    if (t < 32) {
        int acc = 0;
#pragma unroll
        for (int j = 0; j < 4; j++) {
            int idx = t + j * 32;
            if (idx < b) acc += g_blocksums[idx];
        }
#pragma unroll
        for (int off = 16; off > 0; off >>= 1)
            acc += __shfl_down_sync(0xffffffffu, acc, off);
        if (t == 0) s_off = acc;
    }
    __syncthreads();
    int i = blockIdx.x * 1024 + t;
    if (i >= N) return;
    int rs = g_rowstart[i] + s_off;
    g_rowstart[i] = rs;
    g_cursor[i]   = rs;
}

// fill: 1 edge/thread (proven form)
__global__ void k_fill(const void* ei, int E) {
    int e = blockIdx.x * blockDim.x + threadIdx.x;
    if (e >= E) return;
    int s = edge_at(ei, e);
    int d = edge_at(ei, (long long)E + e);
    int pos = atomicAdd(&g_cursor[d], 1);
    if (pos < EMAX) g_csr[pos] = s;
}

// ---- GEMM: h' = dinv * (x_f16 @ W_f16^T) -> fp16
//      A built DIRECTLY from global x into mma fragments (no SMEM for A).
//      W (B operand) via cp.async into 32KB SMEM. 128 rows/CTA, 8 warps 4m x 2n.
#define SM_TOT 32768

__global__ __launch_bounds__(256, 2) void k_gemm_mma(const float* __restrict__ x, int N) {
    extern __shared__ char smem[];
    uint32_t sb = smem_u32(smem);
    int tid = threadIdx.x;
    int row0 = blockIdx.x * 128;

    // ---- W image -> SMEM via cp.async (fire-and-forget) ----
    {
        const char* wsrc = (const char*)g_Wf16_img;
        for (int i = tid; i < 2048; i += 256)
            cpasync16(sb + i * 16, wsrc + i * 16);
        asm volatile("cp.async.commit_group;" ::: "memory");
    }

    int warp = tid >> 5, lane = tid & 31;
    int wm = warp & 3, wn = warp >> 2;
    int m0 = wm * 32, n0 = wn * 64;
    int sub = lane >> 3, lrow = lane & 7;
    int qrow = lane >> 2, c0 = (lane & 3) * 2;

    // A row pointers (clamped; invalid rows discarded at store time)
    const float* xptr[2][2];
    int rbase = row0 + m0 + qrow;
#pragma unroll
    for (int mt = 0; mt < 2; mt++) {
        int r0i = rbase + mt * 16;
        int r1i = r0i + 8;
        xptr[mt][0] = x + (size_t)min(r0i, N - 1) * 128;
        xptr[mt][1] = x + (size_t)min(r1i, N - 1) * 128;
    }

    float acc[2][8][4];
#pragma unroll
    for (int mt = 0; mt < 2; mt++)
#pragma unroll
        for (int nt = 0; nt < 8; nt++)
#pragma unroll
            for (int q = 0; q < 4; q++) acc[mt][nt][q] = 0.f;

    int b_row_off = ((sub & 2) << 2) + lrow;
    int b_halfk   = sub & 1;

    asm volatile("cp.async.wait_group 0;" ::: "memory");
    __syncthreads();

#pragma unroll
    for (int ks = 0; ks < 8; ks++) {
        int kb = ks * 16 + c0;
        uint32_t a[2][4];
#pragma unroll
        for (int mt = 0; mt < 2; mt++) {
            float2 f0 = *(const float2*)(xptr[mt][0] + kb);
            float2 f1 = *(const float2*)(xptr[mt][1] + kb);
            float2 f2 = *(const float2*)(xptr[mt][0] + kb + 8);
            float2 f3 = *(const float2*)(xptr[mt][1] + kb + 8);
            __half2 h0 = __floats2half2_rn(f0.x, f0.y);
            __half2 h1 = __floats2half2_rn(f1.x, f1.y);
            __half2 h2 = __floats2half2_rn(f2.x, f2.y);
            __half2 h3 = __floats2half2_rn(f3.x, f3.y);
            a[mt][0] = *(uint32_t*)&h0;
            a[mt][1] = *(uint32_t*)&h1;
            a[mt][2] = *(uint32_t*)&h2;
            a[mt][3] = *(uint32_t*)&h3;
        }
        uint32_t b[8][2];
#pragma unroll
        for (int np = 0; np < 4; np++) {
            int r = n0 + np * 16 + b_row_off;
            int kc = 2 * ks + b_halfk;
            uint32_t addr = (uint32_t)((r * 16 + (kc ^ (r & 7))) * 16);
            ldm_x4(b[2 * np][0], b[2 * np][1], b[2 * np + 1][0], b[2 * np + 1][1],
                   sb + addr);
        }
#pragma unroll
        for (int mt = 0; mt < 2; mt++)
#pragma unroll
            for (int nt = 0; nt < 8; nt++)
                mma_f16(acc[mt][nt], a[mt], b[nt]);
    }

    // ---- epilogue: prescale rows by dinv, fp16 stores ----
    int qcol = (lane & 3) * 2;
    __half2* h2p = (__half2*)g_hh;
#pragma unroll
    for (int mt = 0; mt < 2; mt++) {
        int r_lo = row0 + m0 + mt * 16 + qrow;
        int r_hi = r_lo + 8;
        float d_lo = (r_lo < N) ? g_dinv[r_lo] : 0.f;
        float d_hi = (r_hi < N) ? g_dinv[r_hi] : 0.f;
#pragma unroll
        for (int nt = 0; nt < 8; nt++) {
            int col = n0 + nt * 8 + qcol;
            if (r_lo < N)
                h2p[(size_t)r_lo * 64 + (col >> 1)] =
                    __floats2half2_rn(d_lo * acc[mt][nt][0], d_lo * acc[mt][nt][1]);
            if (r_hi < N)
                h2p[(size_t)r_hi * 64 + (col >> 1)] =
                    __floats2half2_rn(d_hi * acc[mt][nt][2], d_hi * acc[mt][nt][3]);
        }
    }
}

// ------- aggregation (grid-stride, warp per node) + fused BN statistics ----------
// proven form: 4 independent gathers in flight
__global__ __launch_bounds__(256) void k_agg(const float* __restrict__ bias,
                                             float* __restrict__ out, int N, int totalWarps) {
    __shared__ float sh_sum[128];
    __shared__ float sh_sq[128];
    int tid = threadIdx.x;
    int lane = tid & 31;
    if (tid < 128) { sh_sum[tid] = 0.f; sh_sq[tid] = 0.f; }
    __syncthreads();

    int gwarp = blockIdx.x * 8 + (tid >> 5);
    const uint2* hrow = (const uint2*)g_hh;   // 32 uint2 per 128-half row
    float4 bb = ((const float4*)bias)[lane];
    float4 ssum = make_float4(0.f, 0.f, 0.f, 0.f);
    float4 ssq  = make_float4(0.f, 0.f, 0.f, 0.f);

    for (int node = gwarp; node < N; node += totalWarps) {
        int   base = g_rowstart[node];
        int   cnt  = g_counts[node];
        float di   = g_dinv[node];

        float4 a0, a1, a2, a3;
        {
            uint2 v = hrow[(size_t)node * 32 + lane];
            float2 p0 = __half22float2(*(__half2*)&v.x);
            float2 p1 = __half22float2(*(__half2*)&v.y);
            a0 = make_float4(p0.x, p0.y, p1.x, p1.y);
        }
        a1 = make_float4(0.f, 0.f, 0.f, 0.f);
        a2 = make_float4(0.f, 0.f, 0.f, 0.f);
        a3 = make_float4(0.f, 0.f, 0.f, 0.f);

        for (int j0 = 0; j0 < cnt; j0 += 32) {
            int myj = j0 + lane;
            int s = (myj < cnt) ? g_csr[base + myj] : 0;
            int m = min(32, cnt - j0);
            int t = 0;
            for (; t + 4 <= m; t += 4) {
                int sv0 = __shfl_sync(0xffffffffu, s, t);
                int sv1 = __shfl_sync(0xffffffffu, s, t + 1);
                int sv2 = __shfl_sync(0xffffffffu, s, t + 2);
                int sv3 = __shfl_sync(0xffffffffu, s, t + 3);
                uint2 v0 = hrow[(size_t)sv0 * 32 + lane];
                uint2 v1 = hrow[(size_t)sv1 * 32 + lane];
                uint2 v2 = hrow[(size_t)sv2 * 32 + lane];
                uint2 v3 = hrow[(size_t)sv3 * 32 + lane];
                float2 q0, q1;
                q0 = __half22float2(*(__half2*)&v0.x); q1 = __half22float2(*(__half2*)&v0.y);
                a0.x += q0.x; a0.y += q0.y; a0.z += q1.x; a0.w += q1.y;
                q0 = __half22float2(*(__half2*)&v1.x); q1 = __half22float2(*(__half2*)&v1.y);
                a1.x += q0.x; a1.y += q0.y; a1.z += q1.x; a1.w += q1.y;
                q0 = __half22float2(*(__half2*)&v2.x); q1 = __half22float2(*(__half2*)&v2.y);
                a2.x += q0.x; a2.y += q0.y; a2.z += q1.x; a2.w += q1.y;
                q0 = __half22float2(*(__half2*)&v3.x); q1 = __half22float2(*(__half2*)&v3.y);
                a3.x += q0.x; a3.y += q0.y; a3.z += q1.x; a3.w += q1.y;
            }
            for (; t < m; t++) {
                int sv0 = __shfl_sync(0xffffffffu, s, t);
                uint2 v0 = hrow[(size_t)sv0 * 32 + lane];
                float2 q0 = __half22float2(*(__half2*)&v0.x);
                float2 q1 = __half22float2(*(__half2*)&v0.y);
                a0.x += q0.x; a0.y += q0.y; a0.z += q1.x; a0.w += q1.y;
            }
        }
        float4 o;
        o.x = di * ((a0.x + a1.x) + (a2.x + a3.x)) + bb.x;
        o.y = di * ((a0.y + a1.y) + (a2.y + a3.y)) + bb.y;
        o.z = di * ((a0.z + a1.z) + (a2.z + a3.z)) + bb.z;
        o.w = di * ((a0.w + a1.w) + (a2.w + a3.w)) + bb.w;
        ((float4*)out)[(size_t)node * 32 + lane] = o;
        ssum.x += o.x; ssum.y += o.y; ssum.z += o.z; ssum.w += o.w;
        ssq.x += o.x * o.x; ssq.y += o.y * o.y; ssq.z += o.z * o.z; ssq.w += o.w * o.w;
    }

    atomicAdd(&sh_sum[lane * 4 + 0], ssum.x);
    atomicAdd(&sh_sum[lane * 4 + 1], ssum.y);
    atomicAdd(&sh_sum[lane * 4 + 2], ssum.z);
    atomicAdd(&sh_sum[lane * 4 + 3], ssum.w);
    atomicAdd(&sh_sq[lane * 4 + 0], ssq.x);
    atomicAdd(&sh_sq[lane * 4 + 1], ssq.y);
    atomicAdd(&sh_sq[lane * 4 + 2], ssq.z);
    atomicAdd(&sh_sq[lane * 4 + 3], ssq.w);
    __syncthreads();
    if (tid < 128) {
        atomicAdd(&g_stats[tid], sh_sum[tid]);
        atomicAdd(&g_stats[D + tid], sh_sq[tid]);
    }
}

// ---------------- BN + ReLU + residual -------------------------------------------
__global__ void k_final(const float* __restrict__ x, const float* __restrict__ gamma,
                        const float* __restrict__ beta, float* __restrict__ out, int N) {
    long long i = (long long)blockIdx.x * blockDim.x + threadIdx.x;
    long long total = (long long)N * 32;
    if (i >= total) return;
    int c4 = (int)(i & 31);
    float invN = 1.0f / (float)N;
    float4 v  = ((float4*)out)[i];
    float4 xv = ((const float4*)x)[i];
    float r[4] = {v.x, v.y, v.z, v.w};
    float xr[4] = {xv.x, xv.y, xv.z, xv.w};
#pragma unroll
    for (int c = 0; c < 4; c++) {
        int col = c4 * 4 + c;
        float mu  = g_stats[col] * invN;
        float var = g_stats[D + col] * invN - mu * mu;
        float inv = rsqrtf(var + BN_EPS);
        float y = __ldg(&gamma[col]) * (r[c] - mu) * inv + __ldg(&beta[col]);
        y = fmaxf(y, 0.0f);
        r[c] = y + xr[c];
    }
    ((float4*)out)[i] = make_float4(r[0], r[1], r[2], r[3]);
}

// ---------------- launcher: fork-join graph with GEMM on a side stream -----------
extern "C" void kernel_launch(void* const* d_in, const int* in_sizes, int n_in,
                              void* d_out, int out_size) {
    const float* x     = (const float*)d_in[0];
    const float* W     = (const float*)d_in[1];
    const float* bias  = (const float*)d_in[2];
    const float* gamma = (const float*)d_in[3];
    const float* beta  = (const float*)d_in[4];
    const void*  ei    = d_in[5];
    int N = in_sizes[0] / D;
    int E = in_sizes[5] / 2;
    float* out = (float*)d_out;

    cudaFuncSetAttribute(k_gemm_mma, cudaFuncAttributeMaxDynamicSharedMemorySize, SM_TOT);

    cudaStream_t s2;
    cudaStreamCreate(&s2);
    cudaEvent_t evFork, evJoin;
    cudaEventCreateWithFlags(&evFork, cudaEventDisableTiming);
    cudaEventCreateWithFlags(&evJoin, cudaEventDisableTiming);

    int nblk = (N + 1023) / 1024;
    k_init<<<(N + 255) / 256, 256>>>((const int*)ei, W, E, N);
    k_hist<<<(E + 255) / 256, 256>>>(ei, E);
    k_scan1<<<nblk, 1024>>>(N);

    // fork: GEMM depends only on init(W img) + scan1(dinv)
    cudaEventRecord(evFork, 0);
    cudaStreamWaitEvent(s2, evFork, 0);
    k_gemm_mma<<<(N + 127) / 128, 256, SM_TOT, s2>>>(x, N);
    cudaEventRecord(evJoin, s2);

    // main stream continues with CSR finalize concurrently
    k_scan3<<<nblk, 1024>>>(N);
    k_fill<<<(E + 255) / 256, 256>>>(ei, E);

    // join before aggregation (needs g_hh + g_csr)
    cudaStreamWaitEvent(0, evJoin, 0);
    int aggBlocks = 1036;                       // 7 blocks/SM * 148
    k_agg<<<aggBlocks, 256>>>(bias, out, N, aggBlocks * 8);
    k_final<<<(int)(((long long)N * 32 + 255) / 256), 256>>>(x, gamma, beta, out, N);

    cudaEventDestroy(evFork);
    cudaEventDestroy(evJoin);
    cudaStreamDestroy(s2);
}